// round 1
// baseline (speedup 1.0000x reference)
#include <cuda_runtime.h>
#include <cuda_bf16.h>
#include <cstdint>

// Problem constants (fixed by the reference)
#define BB 2
#define TT 2048
#define DD 1024
#define HH 16
#define DKK 64
#define TD3 3072    // 3*D
#define MM (BB*TT)  // 4096 rows

// Scratch (allocation-free rule: __device__ globals)
__device__ float g_qkv[MM * TD3];   // 48 MB
__device__ float g_y[MM * DD];      // 16 MB

// ---------------------------------------------------------------------------
// Tiled SGEMM with bias: C[M,N] = A[M,K] @ W[K,N] + bias[N]
// BM=BN=64, BK=16, 256 threads, 4x4 micro-tile per thread.
// ---------------------------------------------------------------------------
__global__ __launch_bounds__(256) void sgemm_bias(
    const float* __restrict__ A, const float* __restrict__ W,
    const float* __restrict__ bias, float* __restrict__ C,
    int M, int N, int K)
{
    __shared__ float As[16][64];   // k-major
    __shared__ float Ws[16][64];

    const int tid = threadIdx.x;
    const int tx = tid & 15;       // 0..15 -> N
    const int ty = tid >> 4;       // 0..15 -> M
    const int m0 = blockIdx.y * 64;
    const int n0 = blockIdx.x * 64;

    const int arow = tid >> 2;          // 0..63
    const int acol = (tid & 3) * 4;     // 0,4,8,12
    const int wrow = tid >> 4;          // 0..15
    const int wcol = (tid & 15) * 4;    // 0..60

    float acc[4][4];
#pragma unroll
    for (int i = 0; i < 4; i++)
#pragma unroll
        for (int j = 0; j < 4; j++) acc[i][j] = 0.f;

    for (int k0 = 0; k0 < K; k0 += 16) {
        float4 av = *(const float4*)(A + (size_t)(m0 + arow) * K + k0 + acol);
        float4 wv = *(const float4*)(W + (size_t)(k0 + wrow) * N + n0 + wcol);
        As[acol + 0][arow] = av.x;
        As[acol + 1][arow] = av.y;
        As[acol + 2][arow] = av.z;
        As[acol + 3][arow] = av.w;
        *(float4*)&Ws[wrow][wcol] = wv;
        __syncthreads();

#pragma unroll
        for (int k = 0; k < 16; k++) {
            float4 a = *(const float4*)&As[k][ty * 4];
            float4 b = *(const float4*)&Ws[k][tx * 4];
            float ar[4] = {a.x, a.y, a.z, a.w};
            float br[4] = {b.x, b.y, b.z, b.w};
#pragma unroll
            for (int i = 0; i < 4; i++)
#pragma unroll
                for (int j = 0; j < 4; j++) acc[i][j] += ar[i] * br[j];
        }
        __syncthreads();
    }

#pragma unroll
    for (int i = 0; i < 4; i++) {
        float4 o;
        o.x = acc[i][0] + bias[n0 + tx * 4 + 0];
        o.y = acc[i][1] + bias[n0 + tx * 4 + 1];
        o.z = acc[i][2] + bias[n0 + tx * 4 + 2];
        o.w = acc[i][3] + bias[n0 + tx * 4 + 3];
        *(float4*)(C + (size_t)(m0 + ty * 4 + i) * N + n0 + tx * 4) = o;
    }
}

// ---------------------------------------------------------------------------
// Flash attention (fp32, causal). One block = 64 query rows of one (b,h).
// 256 threads: 4 threads per query row. Online softmax, exp computed once
// per score. q row lives in registers (64 regs), K/V/S tiles in smem with
// stride-65 padding (bank-conflict-free inner loops).
// ---------------------------------------------------------------------------
#define FL_LDS 65
#define FL_SMEM_FLOATS (3 * 64 * FL_LDS + 2 * 64 * 4)
#define FL_SMEM_BYTES (FL_SMEM_FLOATS * 4)

__global__ __launch_bounds__(256) void flash_attn(
    const float* __restrict__ qkv, float* __restrict__ y)
{
    extern __shared__ float sm[];
    float* Ks   = sm;
    float* Vs   = sm + 64 * FL_LDS;
    float* Ss   = sm + 2 * 64 * FL_LDS;
    float* pmax = sm + 3 * 64 * FL_LDS;
    float* psum = pmax + 64 * 4;

    const int tid = threadIdx.x;
    const int r = tid >> 2;     // query row within tile, 0..63
    const int g = tid & 3;      // subgroup: key-group for QK, dim-group for PV
    const int qt = blockIdx.x;
    const int bh = blockIdx.y;
    const int b = bh >> 4;
    const int h = bh & 15;
    const int q0 = qt * 64;

    // q row into registers, pre-scaled by 1/sqrt(DK) = 0.125
    float q[64];
    {
        const float* qptr = qkv + ((size_t)(b * TT + q0 + r)) * TD3 + h * 64;
#pragma unroll
        for (int d = 0; d < 64; d++) q[d] = qptr[d] * 0.125f;
    }

    float acc[16];
#pragma unroll
    for (int i = 0; i < 16; i++) acc[i] = 0.f;
    float m = -1e30f, l = 0.f;

    for (int kt = 0; kt <= qt; kt++) {
        const int k0 = kt * 64;
        // cooperative load of K,V tiles (64x64 each)
#pragma unroll
        for (int u = 0; u < 4; u++) {
            int e = (tid + u * 256) * 4;    // 0..4095 step 4
            int row = e >> 6;
            int col = e & 63;
            const float* kp = qkv + ((size_t)(b * TT + k0 + row)) * TD3 + 1024 + h * 64 + col;
            float4 kv = *(const float4*)kp;
            float4 vv = *(const float4*)(kp + 1024);
            float* kd = Ks + row * FL_LDS + col;
            kd[0] = kv.x; kd[1] = kv.y; kd[2] = kv.z; kd[3] = kv.w;
            float* vd = Vs + row * FL_LDS + col;
            vd[0] = vv.x; vd[1] = vv.y; vd[2] = vv.z; vd[3] = vv.w;
        }
        __syncthreads();

        // ---- scores: this thread handles keys j = jj*4 + g ----
        const bool diag = (kt == qt);
        float pm = -1e30f;
        for (int jj = 0; jj < 16; jj++) {
            int j = jj * 4 + g;
            const float* krow = Ks + j * FL_LDS;
            float s = 0.f;
#pragma unroll
            for (int d = 0; d < 64; d++) s += q[d] * krow[d];
            if (diag && (k0 + j) > (q0 + r)) s = -1e30f;
            Ss[r * FL_LDS + j] = s;
            pm = fmaxf(pm, s);
        }
        pmax[r * 4 + g] = pm;
        __syncthreads();

        float mt = fmaxf(fmaxf(pmax[r * 4 + 0], pmax[r * 4 + 1]),
                         fmaxf(pmax[r * 4 + 2], pmax[r * 4 + 3]));
        float mnew = fmaxf(m, mt);

        // ---- exp pass (each score exp'd exactly once) ----
        float ps = 0.f;
        for (int jj = 0; jj < 16; jj++) {
            int j = jj * 4 + g;
            float p = __expf(Ss[r * FL_LDS + j] - mnew);
            Ss[r * FL_LDS + j] = p;
            ps += p;
        }
        psum[r * 4 + g] = ps;
        __syncthreads();

        float alpha = __expf(m - mnew);
        l = l * alpha + (psum[r * 4 + 0] + psum[r * 4 + 1] +
                         psum[r * 4 + 2] + psum[r * 4 + 3]);
        m = mnew;
#pragma unroll
        for (int i = 0; i < 16; i++) acc[i] *= alpha;

        // ---- PV: this thread handles dims d = i*4 + g ----
        for (int j = 0; j < 64; j++) {
            float p = Ss[r * FL_LDS + j];
            const float* vrow = Vs + j * FL_LDS;
#pragma unroll
            for (int i = 0; i < 16; i++) acc[i] += p * vrow[i * 4 + g];
        }
        __syncthreads();   // protect Ks/Vs/Ss before next tile
    }

    float inv = 1.f / l;
    float* yp = y + ((size_t)(b * TT + q0 + r)) * DD + h * 64;
#pragma unroll
    for (int i = 0; i < 16; i++) yp[i * 4 + g] = acc[i] * inv;
}

// ---------------------------------------------------------------------------
// Launch
// ---------------------------------------------------------------------------
extern "C" void kernel_launch(void* const* d_in, const int* in_sizes, int n_in,
                              void* d_out, int out_size)
{
    const float* x     = (const float*)d_in[0];
    const float* W_qkv = (const float*)d_in[1];
    const float* b_qkv = (const float*)d_in[2];
    const float* W_o   = (const float*)d_in[3];
    const float* b_o   = (const float*)d_in[4];
    float* out = (float*)d_out;

    float* qkv; float* y;
    cudaGetSymbolAddress((void**)&qkv, g_qkv);
    cudaGetSymbolAddress((void**)&y, g_y);

    cudaFuncSetAttribute(flash_attn, cudaFuncAttributeMaxDynamicSharedMemorySize,
                         FL_SMEM_BYTES);

    // 1) QKV projection: [4096,1024] @ [1024,3072] + b
    sgemm_bias<<<dim3(TD3 / 64, MM / 64), 256>>>(x, W_qkv, b_qkv, qkv,
                                                 MM, TD3, DD);
    // 2) causal attention per (b,h), flash style
    flash_attn<<<dim3(TT / 64, BB * HH), 256, FL_SMEM_BYTES>>>(qkv, y);
    // 3) output projection: [4096,1024] @ [1024,1024] + b
    sgemm_bias<<<dim3(DD / 64, MM / 64), 256>>>(y, W_o, b_o, out,
                                                MM, DD, DD);
}

// round 3
// speedup vs baseline: 1.3569x; 1.3569x over previous
#include <cuda_runtime.h>
#include <cuda_bf16.h>
#include <cstdint>

// Problem constants (fixed by the reference)
#define BB 2
#define TT 2048
#define DD 1024
#define HH 16
#define DKK 64
#define TD3 3072    // 3*D
#define MM (BB*TT)  // 4096 rows
#define KK 1024     // GEMM K for both projections

// ---------------------------------------------------------------------------
// Scratch (allocation-free rule: __device__ globals)
// ---------------------------------------------------------------------------
__device__ float g_qkv[MM * TD3];            // 48 MB
__device__ float g_y[MM * DD];               // 16 MB
__device__ __nv_bfloat16 g_xh[MM * KK];      // 8 MB
__device__ __nv_bfloat16 g_xl[MM * KK];
__device__ __nv_bfloat16 g_yh[MM * KK];
__device__ __nv_bfloat16 g_yl[MM * KK];
__device__ __nv_bfloat16 g_wqh[TD3 * KK];    // W_qkv^T split, [N][K]
__device__ __nv_bfloat16 g_wql[TD3 * KK];
__device__ __nv_bfloat16 g_woh[DD * KK];     // W_o^T split
__device__ __nv_bfloat16 g_wol[DD * KK];

// ---------------------------------------------------------------------------
// PTX helpers (plain sm_100-legal: cp.async + ldmatrix + mma.sync)
// ---------------------------------------------------------------------------
__device__ __forceinline__ uint32_t smem_u32(const void* p) {
    uint32_t a;
    asm("{ .reg .u64 t; cvta.to.shared.u64 t, %1; cvt.u32.u64 %0, t; }"
        : "=r"(a) : "l"(p));
    return a;
}
__device__ __forceinline__ void cp16(uint32_t dst, const void* src) {
    asm volatile("cp.async.cg.shared.global [%0], [%1], 16;" :: "r"(dst), "l"(src));
}
__device__ __forceinline__ void cp_commit() {
    asm volatile("cp.async.commit_group;" ::: "memory");
}
template <int N>
__device__ __forceinline__ void cp_wait() {
    asm volatile("cp.async.wait_group %0;" :: "n"(N) : "memory");
}
__device__ __forceinline__ void ldm4(uint32_t* r, uint32_t addr) {
    asm volatile("ldmatrix.sync.aligned.m8n8.x4.shared.b16 {%0,%1,%2,%3}, [%4];"
                 : "=r"(r[0]), "=r"(r[1]), "=r"(r[2]), "=r"(r[3]) : "r"(addr));
}
__device__ __forceinline__ void mma16816(float* c, const uint32_t* a,
                                         const uint32_t* b) {
    asm volatile(
        "mma.sync.aligned.m16n8k16.row.col.f32.bf16.bf16.f32 "
        "{%0,%1,%2,%3}, {%4,%5,%6,%7}, {%8,%9}, {%0,%1,%2,%3};"
        : "+f"(c[0]), "+f"(c[1]), "+f"(c[2]), "+f"(c[3])
        : "r"(a[0]), "r"(a[1]), "r"(a[2]), "r"(a[3]), "r"(b[0]), "r"(b[1]));
}

// ---------------------------------------------------------------------------
// Conversion kernels: fp32 -> (hi, lo) bf16 split
// ---------------------------------------------------------------------------
struct __align__(8) bf4 { __nv_bfloat16 v[4]; };

__global__ __launch_bounds__(256) void split_f32(
    const float* __restrict__ src, __nv_bfloat16* __restrict__ hi,
    __nv_bfloat16* __restrict__ lo, int n)
{
    int i = (blockIdx.x * blockDim.x + threadIdx.x) * 4;
    if (i >= n) return;
    float4 v = *(const float4*)(src + i);
    bf4 h, l;
    float vv[4] = {v.x, v.y, v.z, v.w};
#pragma unroll
    for (int j = 0; j < 4; j++) {
        __nv_bfloat16 a = __float2bfloat16(vv[j]);
        h.v[j] = a;
        l.v[j] = __float2bfloat16(vv[j] - __bfloat162float(a));
    }
    *(bf4*)(hi + i) = h;
    *(bf4*)(lo + i) = l;
}

// W [K][N] fp32 -> Wt_hi/lo [N][K] bf16 (transpose + split)
__global__ __launch_bounds__(256) void split_transpose(
    const float* __restrict__ W, __nv_bfloat16* __restrict__ Thi,
    __nv_bfloat16* __restrict__ Tlo, int K, int N)
{
    __shared__ float t[32][33];
    int n0 = blockIdx.x * 32, k0 = blockIdx.y * 32;
    int tx = threadIdx.x, ty = threadIdx.y;
#pragma unroll
    for (int i = ty; i < 32; i += 8)
        t[i][tx] = W[(size_t)(k0 + i) * N + n0 + tx];
    __syncthreads();
#pragma unroll
    for (int i = ty; i < 32; i += 8) {
        float v = t[tx][i];    // k = k0+tx, n = n0+i
        __nv_bfloat16 h = __float2bfloat16(v);
        Thi[(size_t)(n0 + i) * K + k0 + tx] = h;
        Tlo[(size_t)(n0 + i) * K + k0 + tx] =
            __float2bfloat16(v - __bfloat162float(h));
    }
}

// ---------------------------------------------------------------------------
// mma.sync GEMM: C[M,N] = A[M,K] @ Wt[N,K]^T + bias, split-bf16 x3.
// 128x128 tile / CTA, BK=32, cp.async double buffer, 8 warps (4m x 2n),
// warp tile 32x64. Smem rows 64B with XOR-chunk swizzle (ldmatrix
// bank-conflict-free).
// ---------------------------------------------------------------------------
#define TILE_B 8192                    // 128 rows * 64 B
#define STAGE_B (4 * TILE_B)           // Ahi, Alo, Bhi, Blo
#define GSMEM_BYTES (2 * STAGE_B)      // 65536
#define NCHUNK (KK / 32)               // 32

// swizzled byte offset within a tile for (row, 16B-chunk)
__device__ __forceinline__ uint32_t swz_off(int row, int chunk) {
    return (uint32_t)(row * 64 + ((chunk ^ ((row >> 1) & 3)) << 4));
}

__device__ __forceinline__ void load_stage(
    uint32_t sb, int s, int k0,
    const __nv_bfloat16* __restrict__ Ahi, const __nv_bfloat16* __restrict__ Alo,
    const __nv_bfloat16* __restrict__ Bhi, const __nv_bfloat16* __restrict__ Blo,
    int m0, int n0, int tid)
{
    uint32_t base = sb + (uint32_t)s * STAGE_B;
    const __nv_bfloat16* srcs[4] = {Ahi, Alo, Bhi, Blo};
    int r0s[4] = {m0, m0, n0, n0};
#pragma unroll
    for (int t = 0; t < 4; t++) {
        const __nv_bfloat16* p = srcs[t];
        int r0 = r0s[t];
        uint32_t tb = base + t * TILE_B;
#pragma unroll
        for (int i = 0; i < 2; i++) {
            int c = tid + i * 256;          // 0..511
            int row = c >> 2;
            int ch = c & 3;
            const void* g = p + (size_t)(r0 + row) * KK + k0 + ch * 8;
            cp16(tb + swz_off(row, ch), g);
        }
    }
    cp_commit();
}

__global__ __launch_bounds__(256) void gemm_mma(
    const __nv_bfloat16* __restrict__ Ahi, const __nv_bfloat16* __restrict__ Alo,
    const __nv_bfloat16* __restrict__ Bhi, const __nv_bfloat16* __restrict__ Blo,
    const float* __restrict__ bias, float* __restrict__ C, int N)
{
    extern __shared__ char smem[];
    uint32_t sb = smem_u32(smem);
    const int tid = threadIdx.x;
    const int wid = tid >> 5;
    const int lane = tid & 31;
    const int warp_m = wid >> 1;       // 0..3  -> 32-row slab
    const int warp_n = wid & 1;        // 0..1  -> 64-col slab
    const int n0 = blockIdx.x * 128;
    const int m0 = blockIdx.y * 128;

    float acc[2][8][4];
#pragma unroll
    for (int i = 0; i < 2; i++)
#pragma unroll
        for (int j = 0; j < 8; j++)
#pragma unroll
            for (int k = 0; k < 4; k++) acc[i][j][k] = 0.f;

    load_stage(sb, 0, 0, Ahi, Alo, Bhi, Blo, m0, n0, tid);

    for (int c = 0; c < NCHUNK; c++) {
        int s = c & 1;
        if (c + 1 < NCHUNK) {
            load_stage(sb, s ^ 1, (c + 1) * 32, Ahi, Alo, Bhi, Blo, m0, n0, tid);
            cp_wait<1>();
        } else {
            cp_wait<0>();
        }
        __syncthreads();

        uint32_t abase = sb + (uint32_t)s * STAGE_B;
#pragma unroll
        for (int ks = 0; ks < 2; ks++) {
            uint32_t ah[2][4], al[2][4], bh[4][4], bl[4][4];
#pragma unroll
            for (int mt = 0; mt < 2; mt++) {
                int row = warp_m * 32 + mt * 16 + (lane & 15);
                int ch = ks * 2 + (lane >> 4);
                uint32_t off = swz_off(row, ch);
                ldm4(ah[mt], abase + off);
                ldm4(al[mt], abase + TILE_B + off);
            }
#pragma unroll
            for (int p = 0; p < 4; p++) {
                int row = warp_n * 64 + (p * 2 + (lane >> 4)) * 8 + (lane & 7);
                int ch = ks * 2 + ((lane >> 3) & 1);
                uint32_t off = swz_off(row, ch);
                ldm4(bh[p], abase + 2 * TILE_B + off);
                ldm4(bl[p], abase + 3 * TILE_B + off);
            }
#pragma unroll
            for (int mt = 0; mt < 2; mt++)
#pragma unroll
                for (int nt = 0; nt < 8; nt++) {
                    const uint32_t* bhp = &bh[nt >> 1][(nt & 1) * 2];
                    const uint32_t* blp = &bl[nt >> 1][(nt & 1) * 2];
                    mma16816(acc[mt][nt], ah[mt], bhp);
                    mma16816(acc[mt][nt], al[mt], bhp);
                    mma16816(acc[mt][nt], ah[mt], blp);
                }
        }
        __syncthreads();
    }

    // Epilogue: c-frag (m16n8): {c0,c1} at (row t/4, col (t%4)*2), {c2,c3} +8 rows
#pragma unroll
    for (int mt = 0; mt < 2; mt++) {
        int m = m0 + warp_m * 32 + mt * 16 + (lane >> 2);
#pragma unroll
        for (int nt = 0; nt < 8; nt++) {
            int n = n0 + warp_n * 64 + nt * 8 + (lane & 3) * 2;
            float b0 = bias[n], b1 = bias[n + 1];
            float2 o0 = {acc[mt][nt][0] + b0, acc[mt][nt][1] + b1};
            float2 o1 = {acc[mt][nt][2] + b0, acc[mt][nt][3] + b1};
            *(float2*)(C + (size_t)m * N + n) = o0;
            *(float2*)(C + (size_t)(m + 8) * N + n) = o1;
        }
    }
}

// ---------------------------------------------------------------------------
// Flash attention (fp32, causal) — unchanged from R1 (proven correct).
// ---------------------------------------------------------------------------
#define FL_LDS 65
#define FL_SMEM_FLOATS (3 * 64 * FL_LDS + 2 * 64 * 4)
#define FL_SMEM_BYTES (FL_SMEM_FLOATS * 4)

__global__ __launch_bounds__(256) void flash_attn(
    const float* __restrict__ qkv, float* __restrict__ y)
{
    extern __shared__ float sm[];
    float* Ks   = sm;
    float* Vs   = sm + 64 * FL_LDS;
    float* Ss   = sm + 2 * 64 * FL_LDS;
    float* pmax = sm + 3 * 64 * FL_LDS;
    float* psum = pmax + 64 * 4;

    const int tid = threadIdx.x;
    const int r = tid >> 2;
    const int g = tid & 3;
    const int qt = blockIdx.x;
    const int bh = blockIdx.y;
    const int b = bh >> 4;
    const int h = bh & 15;
    const int q0 = qt * 64;

    float q[64];
    {
        const float* qptr = qkv + ((size_t)(b * TT + q0 + r)) * TD3 + h * 64;
#pragma unroll
        for (int d = 0; d < 64; d++) q[d] = qptr[d] * 0.125f;
    }

    float acc[16];
#pragma unroll
    for (int i = 0; i < 16; i++) acc[i] = 0.f;
    float m = -1e30f, l = 0.f;

    for (int kt = 0; kt <= qt; kt++) {
        const int k0 = kt * 64;
#pragma unroll
        for (int u = 0; u < 4; u++) {
            int e = (tid + u * 256) * 4;
            int row = e >> 6;
            int col = e & 63;
            const float* kp = qkv + ((size_t)(b * TT + k0 + row)) * TD3 + 1024 + h * 64 + col;
            float4 kv = *(const float4*)kp;
            float4 vv = *(const float4*)(kp + 1024);
            float* kd = Ks + row * FL_LDS + col;
            kd[0] = kv.x; kd[1] = kv.y; kd[2] = kv.z; kd[3] = kv.w;
            float* vd = Vs + row * FL_LDS + col;
            vd[0] = vv.x; vd[1] = vv.y; vd[2] = vv.z; vd[3] = vv.w;
        }
        __syncthreads();

        const bool diag = (kt == qt);
        float pm = -1e30f;
        for (int jj = 0; jj < 16; jj++) {
            int j = jj * 4 + g;
            const float* krow = Ks + j * FL_LDS;
            float s = 0.f;
#pragma unroll
            for (int d = 0; d < 64; d++) s += q[d] * krow[d];
            if (diag && (k0 + j) > (q0 + r)) s = -1e30f;
            Ss[r * FL_LDS + j] = s;
            pm = fmaxf(pm, s);
        }
        pmax[r * 4 + g] = pm;
        __syncthreads();

        float mt = fmaxf(fmaxf(pmax[r * 4 + 0], pmax[r * 4 + 1]),
                         fmaxf(pmax[r * 4 + 2], pmax[r * 4 + 3]));
        float mnew = fmaxf(m, mt);

        float ps = 0.f;
        for (int jj = 0; jj < 16; jj++) {
            int j = jj * 4 + g;
            float p = __expf(Ss[r * FL_LDS + j] - mnew);
            Ss[r * FL_LDS + j] = p;
            ps += p;
        }
        psum[r * 4 + g] = ps;
        __syncthreads();

        float alpha = __expf(m - mnew);
        l = l * alpha + (psum[r * 4 + 0] + psum[r * 4 + 1] +
                         psum[r * 4 + 2] + psum[r * 4 + 3]);
        m = mnew;
#pragma unroll
        for (int i = 0; i < 16; i++) acc[i] *= alpha;

        for (int j = 0; j < 64; j++) {
            float p = Ss[r * FL_LDS + j];
            const float* vrow = Vs + j * FL_LDS;
#pragma unroll
            for (int i = 0; i < 16; i++) acc[i] += p * vrow[i * 4 + g];
        }
        __syncthreads();
    }

    float inv = 1.f / l;
    float* yp = y + ((size_t)(b * TT + q0 + r)) * DD + h * 64;
#pragma unroll
    for (int i = 0; i < 16; i++) yp[i * 4 + g] = acc[i] * inv;
}

// ---------------------------------------------------------------------------
// Launch
// ---------------------------------------------------------------------------
extern "C" void kernel_launch(void* const* d_in, const int* in_sizes, int n_in,
                              void* d_out, int out_size)
{
    const float* x     = (const float*)d_in[0];
    const float* W_qkv = (const float*)d_in[1];
    const float* b_qkv = (const float*)d_in[2];
    const float* W_o   = (const float*)d_in[3];
    const float* b_o   = (const float*)d_in[4];
    float* out = (float*)d_out;

    float *qkv, *y;
    __nv_bfloat16 *xh, *xl, *yh, *yl, *wqh, *wql, *woh, *wol;
    cudaGetSymbolAddress((void**)&qkv, g_qkv);
    cudaGetSymbolAddress((void**)&y, g_y);
    cudaGetSymbolAddress((void**)&xh, g_xh);
    cudaGetSymbolAddress((void**)&xl, g_xl);
    cudaGetSymbolAddress((void**)&yh, g_yh);
    cudaGetSymbolAddress((void**)&yl, g_yl);
    cudaGetSymbolAddress((void**)&wqh, g_wqh);
    cudaGetSymbolAddress((void**)&wql, g_wql);
    cudaGetSymbolAddress((void**)&woh, g_woh);
    cudaGetSymbolAddress((void**)&wol, g_wol);

    cudaFuncSetAttribute(flash_attn, cudaFuncAttributeMaxDynamicSharedMemorySize,
                         FL_SMEM_BYTES);
    cudaFuncSetAttribute(gemm_mma, cudaFuncAttributeMaxDynamicSharedMemorySize,
                         GSMEM_BYTES);

    // conversions
    split_f32<<<(MM * KK / 4 + 255) / 256, 256>>>(x, xh, xl, MM * KK);
    split_transpose<<<dim3(TD3 / 32, KK / 32), dim3(32, 8)>>>(W_qkv, wqh, wql, KK, TD3);
    split_transpose<<<dim3(DD / 32, KK / 32), dim3(32, 8)>>>(W_o, woh, wol, KK, DD);

    // 1) QKV projection (tensor cores via mma.sync)
    gemm_mma<<<dim3(TD3 / 128, MM / 128), 256, GSMEM_BYTES>>>(
        xh, xl, wqh, wql, b_qkv, qkv, TD3);

    // 2) causal flash attention (fp32)
    flash_attn<<<dim3(TT / 64, BB * HH), 256, FL_SMEM_BYTES>>>(qkv, y);

    // 3) output projection (tensor cores via mma.sync)
    split_f32<<<(MM * KK / 4 + 255) / 256, 256>>>(y, yh, yl, MM * KK);
    gemm_mma<<<dim3(DD / 128, MM / 128), 256, GSMEM_BYTES>>>(
        yh, yl, woh, wol, b_o, out, DD);
}

// round 4
// speedup vs baseline: 4.5598x; 3.3604x over previous
#include <cuda_runtime.h>
#include <cuda_bf16.h>
#include <cstdint>

// Problem constants (fixed by the reference)
#define BB 2
#define TT 2048
#define DD 1024
#define HH 16
#define DKK 64
#define TD3 3072    // 3*D
#define MM (BB*TT)  // 4096 rows
#define KK 1024     // GEMM K for both projections

// ---------------------------------------------------------------------------
// Scratch (allocation-free rule: __device__ globals)
// ---------------------------------------------------------------------------
__device__ __nv_bfloat16 g_qkvh[MM * TD3];   // 24 MB  qkv hi
__device__ __nv_bfloat16 g_qkvl[MM * TD3];   // 24 MB  qkv lo
__device__ __nv_bfloat16 g_xh[MM * KK];
__device__ __nv_bfloat16 g_xl[MM * KK];
__device__ __nv_bfloat16 g_yh[MM * KK];      // attention out hi
__device__ __nv_bfloat16 g_yl[MM * KK];      // attention out lo
__device__ __nv_bfloat16 g_wqh[TD3 * KK];    // W_qkv^T split, [N][K]
__device__ __nv_bfloat16 g_wql[TD3 * KK];
__device__ __nv_bfloat16 g_woh[DD * KK];     // W_o^T split
__device__ __nv_bfloat16 g_wol[DD * KK];

// ---------------------------------------------------------------------------
// PTX helpers (plain sm_100-legal: cp.async + ldmatrix + mma.sync)
// ---------------------------------------------------------------------------
__device__ __forceinline__ uint32_t smem_u32(const void* p) {
    uint32_t a;
    asm("{ .reg .u64 t; cvta.to.shared.u64 t, %1; cvt.u32.u64 %0, t; }"
        : "=r"(a) : "l"(p));
    return a;
}
__device__ __forceinline__ void cp16(uint32_t dst, const void* src) {
    asm volatile("cp.async.cg.shared.global [%0], [%1], 16;" :: "r"(dst), "l"(src));
}
__device__ __forceinline__ void cp_commit() {
    asm volatile("cp.async.commit_group;" ::: "memory");
}
template <int N>
__device__ __forceinline__ void cp_wait() {
    asm volatile("cp.async.wait_group %0;" :: "n"(N) : "memory");
}
__device__ __forceinline__ void ldm4(uint32_t* r, uint32_t addr) {
    asm volatile("ldmatrix.sync.aligned.m8n8.x4.shared.b16 {%0,%1,%2,%3}, [%4];"
                 : "=r"(r[0]), "=r"(r[1]), "=r"(r[2]), "=r"(r[3]) : "r"(addr));
}
__device__ __forceinline__ void ldm4t(uint32_t* r, uint32_t addr) {
    asm volatile("ldmatrix.sync.aligned.m8n8.x4.trans.shared.b16 {%0,%1,%2,%3}, [%4];"
                 : "=r"(r[0]), "=r"(r[1]), "=r"(r[2]), "=r"(r[3]) : "r"(addr));
}
__device__ __forceinline__ void mma16816(float* c, const uint32_t* a,
                                         const uint32_t* b) {
    asm volatile(
        "mma.sync.aligned.m16n8k16.row.col.f32.bf16.bf16.f32 "
        "{%0,%1,%2,%3}, {%4,%5,%6,%7}, {%8,%9}, {%0,%1,%2,%3};"
        : "+f"(c[0]), "+f"(c[1]), "+f"(c[2]), "+f"(c[3])
        : "r"(a[0]), "r"(a[1]), "r"(a[2]), "r"(a[3]), "r"(b[0]), "r"(b[1]));
}
__device__ __forceinline__ uint32_t pack_bf16(float a, float b) {
    __nv_bfloat162 t = __floats2bfloat162_rn(a, b);  // .x = a (low)
    return *(uint32_t*)&t;
}

// ---------------------------------------------------------------------------
// Conversion kernels: fp32 -> (hi, lo) bf16 split
// ---------------------------------------------------------------------------
struct __align__(8) bf4 { __nv_bfloat16 v[4]; };

__global__ __launch_bounds__(256) void split_f32(
    const float* __restrict__ src, __nv_bfloat16* __restrict__ hi,
    __nv_bfloat16* __restrict__ lo, int n)
{
    int i = (blockIdx.x * blockDim.x + threadIdx.x) * 4;
    if (i >= n) return;
    float4 v = *(const float4*)(src + i);
    bf4 h, l;
    float vv[4] = {v.x, v.y, v.z, v.w};
#pragma unroll
    for (int j = 0; j < 4; j++) {
        __nv_bfloat16 a = __float2bfloat16(vv[j]);
        h.v[j] = a;
        l.v[j] = __float2bfloat16(vv[j] - __bfloat162float(a));
    }
    *(bf4*)(hi + i) = h;
    *(bf4*)(lo + i) = l;
}

// W [K][N] fp32 -> Wt_hi/lo [N][K] bf16 (transpose + split)
__global__ __launch_bounds__(256) void split_transpose(
    const float* __restrict__ W, __nv_bfloat16* __restrict__ Thi,
    __nv_bfloat16* __restrict__ Tlo, int K, int N)
{
    __shared__ float t[32][33];
    int n0 = blockIdx.x * 32, k0 = blockIdx.y * 32;
    int tx = threadIdx.x, ty = threadIdx.y;
#pragma unroll
    for (int i = ty; i < 32; i += 8)
        t[i][tx] = W[(size_t)(k0 + i) * N + n0 + tx];
    __syncthreads();
#pragma unroll
    for (int i = ty; i < 32; i += 8) {
        float v = t[tx][i];
        __nv_bfloat16 h = __float2bfloat16(v);
        Thi[(size_t)(n0 + i) * K + k0 + tx] = h;
        Tlo[(size_t)(n0 + i) * K + k0 + tx] =
            __float2bfloat16(v - __bfloat162float(h));
    }
}

// ---------------------------------------------------------------------------
// mma.sync GEMM (split-bf16 x3). Templated epilogue: SPLIT_OUT writes bf16
// hi/lo arrays; otherwise fp32 C. Same validated core as R3.
// ---------------------------------------------------------------------------
#define TILE_B 8192                    // 128 rows * 64 B
#define STAGE_B (4 * TILE_B)
#define GSMEM_BYTES (2 * STAGE_B)      // 65536
#define NCHUNK (KK / 32)               // 32

__device__ __forceinline__ uint32_t swz_off(int row, int chunk) {
    return (uint32_t)(row * 64 + ((chunk ^ ((row >> 1) & 3)) << 4));
}

__device__ __forceinline__ void load_stage(
    uint32_t sb, int s, int k0,
    const __nv_bfloat16* __restrict__ Ahi, const __nv_bfloat16* __restrict__ Alo,
    const __nv_bfloat16* __restrict__ Bhi, const __nv_bfloat16* __restrict__ Blo,
    int m0, int n0, int tid)
{
    uint32_t base = sb + (uint32_t)s * STAGE_B;
    const __nv_bfloat16* srcs[4] = {Ahi, Alo, Bhi, Blo};
    int r0s[4] = {m0, m0, n0, n0};
#pragma unroll
    for (int t = 0; t < 4; t++) {
        const __nv_bfloat16* p = srcs[t];
        int r0 = r0s[t];
        uint32_t tb = base + t * TILE_B;
#pragma unroll
        for (int i = 0; i < 2; i++) {
            int c = tid + i * 256;
            int row = c >> 2;
            int ch = c & 3;
            const void* g = p + (size_t)(r0 + row) * KK + k0 + ch * 8;
            cp16(tb + swz_off(row, ch), g);
        }
    }
    cp_commit();
}

template <bool SPLIT_OUT>
__global__ __launch_bounds__(256) void gemm_mma(
    const __nv_bfloat16* __restrict__ Ahi, const __nv_bfloat16* __restrict__ Alo,
    const __nv_bfloat16* __restrict__ Bhi, const __nv_bfloat16* __restrict__ Blo,
    const float* __restrict__ bias, float* __restrict__ C,
    __nv_bfloat16* __restrict__ Ch, __nv_bfloat16* __restrict__ Cl, int N)
{
    extern __shared__ char smem[];
    uint32_t sb = smem_u32(smem);
    const int tid = threadIdx.x;
    const int wid = tid >> 5;
    const int lane = tid & 31;
    const int warp_m = wid >> 1;
    const int warp_n = wid & 1;
    const int n0 = blockIdx.x * 128;
    const int m0 = blockIdx.y * 128;

    float acc[2][8][4];
#pragma unroll
    for (int i = 0; i < 2; i++)
#pragma unroll
        for (int j = 0; j < 8; j++)
#pragma unroll
            for (int k = 0; k < 4; k++) acc[i][j][k] = 0.f;

    load_stage(sb, 0, 0, Ahi, Alo, Bhi, Blo, m0, n0, tid);

    for (int c = 0; c < NCHUNK; c++) {
        int s = c & 1;
        if (c + 1 < NCHUNK) {
            load_stage(sb, s ^ 1, (c + 1) * 32, Ahi, Alo, Bhi, Blo, m0, n0, tid);
            cp_wait<1>();
        } else {
            cp_wait<0>();
        }
        __syncthreads();

        uint32_t abase = sb + (uint32_t)s * STAGE_B;
#pragma unroll
        for (int ks = 0; ks < 2; ks++) {
            uint32_t ah[2][4], al[2][4], bh[4][4], bl[4][4];
#pragma unroll
            for (int mt = 0; mt < 2; mt++) {
                int row = warp_m * 32 + mt * 16 + (lane & 15);
                int ch = ks * 2 + (lane >> 4);
                uint32_t off = swz_off(row, ch);
                ldm4(ah[mt], abase + off);
                ldm4(al[mt], abase + TILE_B + off);
            }
#pragma unroll
            for (int p = 0; p < 4; p++) {
                int row = warp_n * 64 + (p * 2 + (lane >> 4)) * 8 + (lane & 7);
                int ch = ks * 2 + ((lane >> 3) & 1);
                uint32_t off = swz_off(row, ch);
                ldm4(bh[p], abase + 2 * TILE_B + off);
                ldm4(bl[p], abase + 3 * TILE_B + off);
            }
#pragma unroll
            for (int mt = 0; mt < 2; mt++)
#pragma unroll
                for (int nt = 0; nt < 8; nt++) {
                    const uint32_t* bhp = &bh[nt >> 1][(nt & 1) * 2];
                    const uint32_t* blp = &bl[nt >> 1][(nt & 1) * 2];
                    mma16816(acc[mt][nt], ah[mt], bhp);
                    mma16816(acc[mt][nt], al[mt], bhp);
                    mma16816(acc[mt][nt], ah[mt], blp);
                }
        }
        __syncthreads();
    }

#pragma unroll
    for (int mt = 0; mt < 2; mt++) {
        int m = m0 + warp_m * 32 + mt * 16 + (lane >> 2);
#pragma unroll
        for (int nt = 0; nt < 8; nt++) {
            int n = n0 + warp_n * 64 + nt * 8 + (lane & 3) * 2;
            float b0 = bias[n], b1 = bias[n + 1];
            float f0 = acc[mt][nt][0] + b0, f1 = acc[mt][nt][1] + b1;
            float f2 = acc[mt][nt][2] + b0, f3 = acc[mt][nt][3] + b1;
            if (SPLIT_OUT) {
                __nv_bfloat16 h0 = __float2bfloat16(f0), h1 = __float2bfloat16(f1);
                __nv_bfloat16 h2 = __float2bfloat16(f2), h3 = __float2bfloat16(f3);
                uint32_t hp0 = pack_bf16(__bfloat162float(h0), __bfloat162float(h1));
                uint32_t hp1 = pack_bf16(__bfloat162float(h2), __bfloat162float(h3));
                uint32_t lp0 = pack_bf16(f0 - __bfloat162float(h0),
                                         f1 - __bfloat162float(h1));
                uint32_t lp1 = pack_bf16(f2 - __bfloat162float(h2),
                                         f3 - __bfloat162float(h3));
                *(uint32_t*)(Ch + (size_t)m * N + n) = hp0;
                *(uint32_t*)(Ch + (size_t)(m + 8) * N + n) = hp1;
                *(uint32_t*)(Cl + (size_t)m * N + n) = lp0;
                *(uint32_t*)(Cl + (size_t)(m + 8) * N + n) = lp1;
            } else {
                float2 o0 = {f0, f1}, o1 = {f2, f3};
                *(float2*)(C + (size_t)m * N + n) = o0;
                *(float2*)(C + (size_t)(m + 8) * N + n) = o1;
            }
        }
    }
}

// ---------------------------------------------------------------------------
// Tensor-core flash attention (causal). BM=128 (8 warps x m16), BN=64,
// split-bf16 x3 for both QK^T and PV. K/V hi/lo double-buffered in smem,
// 128B rows with XOR-8 swizzle. V fragments via ldmatrix.trans.
// ---------------------------------------------------------------------------
#define FA_TILE_B 8192                  // 64 rows * 128 B
#define FA_STAGE_B (4 * FA_TILE_B)      // Kh, Kl, Vh, Vl
#define FA_SMEM (2 * FA_STAGE_B)        // 65536

__device__ __forceinline__ uint32_t fswz(int row, int ch) {
    return (uint32_t)(row * 128 + ((ch ^ (row & 7)) << 4));
}

__device__ __forceinline__ void fa_load(
    uint32_t sb, int s, int k0,
    const __nv_bfloat16* __restrict__ qh, const __nv_bfloat16* __restrict__ ql,
    int b, int h, int tid)
{
    uint32_t base = sb + (uint32_t)s * FA_STAGE_B;
    const __nv_bfloat16* ptrs[4] = {qh, ql, qh, ql};
    int goff[4] = {1024, 1024, 2048, 2048};   // K from hi/lo, V from hi/lo
#pragma unroll
    for (int t = 0; t < 4; t++) {
        const __nv_bfloat16* p = ptrs[t];
        uint32_t tb = base + t * FA_TILE_B;
#pragma unroll
        for (int i = 0; i < 2; i++) {
            int idx = tid + i * 256;
            int row = idx >> 3;
            int ch = idx & 7;
            const void* g = p + (size_t)(b * TT + k0 + row) * TD3 + goff[t]
                          + h * 64 + ch * 8;
            cp16(tb + fswz(row, ch), g);
        }
    }
    cp_commit();
}

__global__ __launch_bounds__(256, 1) void flash_tc(
    const __nv_bfloat16* __restrict__ qkvh, const __nv_bfloat16* __restrict__ qkvl,
    __nv_bfloat16* __restrict__ yh, __nv_bfloat16* __restrict__ yl)
{
    extern __shared__ char smem[];
    uint32_t sb = smem_u32(smem);
    const int tid = threadIdx.x;
    const int wid = tid >> 5;
    const int lane = tid & 31;
    const int qt = (int)gridDim.x - 1 - (int)blockIdx.x;   // big tiles first
    const int bh = blockIdx.y;
    const int b = bh >> 4;
    const int h = bh & 15;
    const int q0 = qt * 128;

    // ---- Q fragments (hi/lo) straight from gmem ----
    uint32_t qfh[4][4], qfl[4][4];
    {
        size_t r0g = (size_t)(b * TT + q0 + wid * 16 + (lane >> 2));
        const uint32_t* p0h = (const uint32_t*)(qkvh + r0g * TD3 + h * 64);
        const uint32_t* p1h = (const uint32_t*)(qkvh + (r0g + 8) * TD3 + h * 64);
        const uint32_t* p0l = (const uint32_t*)(qkvl + r0g * TD3 + h * 64);
        const uint32_t* p1l = (const uint32_t*)(qkvl + (r0g + 8) * TD3 + h * 64);
        int c2 = lane & 3;
#pragma unroll
        for (int ks = 0; ks < 4; ks++) {
            qfh[ks][0] = p0h[ks * 8 + c2];
            qfh[ks][1] = p1h[ks * 8 + c2];
            qfh[ks][2] = p0h[ks * 8 + c2 + 4];
            qfh[ks][3] = p1h[ks * 8 + c2 + 4];
            qfl[ks][0] = p0l[ks * 8 + c2];
            qfl[ks][1] = p1l[ks * 8 + c2];
            qfl[ks][2] = p0l[ks * 8 + c2 + 4];
            qfl[ks][3] = p1l[ks * 8 + c2 + 4];
        }
    }

    float acc_o[8][4];
#pragma unroll
    for (int i = 0; i < 8; i++)
#pragma unroll
        for (int j = 0; j < 4; j++) acc_o[i][j] = 0.f;
    float mr0 = -1e30f, mr1 = -1e30f, lr0 = 0.f, lr1 = 0.f;

    const int ntile = 2 * (qt + 1);
    fa_load(sb, 0, 0, qkvh, qkvl, b, h, tid);

    for (int kt = 0; kt < ntile; kt++) {
        const int s = kt & 1;
        const int k0 = kt * 64;
        if (kt + 1 < ntile) {
            fa_load(sb, s ^ 1, (kt + 1) * 64, qkvh, qkvl, b, h, tid);
            cp_wait<1>();
        } else {
            cp_wait<0>();
        }
        __syncthreads();

        uint32_t Kb = sb + (uint32_t)s * FA_STAGE_B;
        uint32_t Vb = Kb + 2 * FA_TILE_B;

        // ---- S = Q K^T (split x3) ----
        float accs[8][4];
#pragma unroll
        for (int i = 0; i < 8; i++)
#pragma unroll
            for (int j = 0; j < 4; j++) accs[i][j] = 0.f;

#pragma unroll
        for (int ks = 0; ks < 4; ks++) {
            uint32_t kfh[4][4], kfl[4][4];
#pragma unroll
            for (int j = 0; j < 4; j++) {
                int g = lane >> 3;
                int nt = 2 * j + (g >> 1);
                int kh = g & 1;
                int row = nt * 8 + (lane & 7);
                uint32_t off = fswz(row, ks * 2 + kh);
                ldm4(kfh[j], Kb + off);
                ldm4(kfl[j], Kb + FA_TILE_B + off);
            }
#pragma unroll
            for (int nt = 0; nt < 8; nt++) {
                const uint32_t* bhp = &kfh[nt >> 1][(nt & 1) * 2];
                const uint32_t* blp = &kfl[nt >> 1][(nt & 1) * 2];
                mma16816(accs[nt], qfh[ks], bhp);
                mma16816(accs[nt], qfl[ks], bhp);
                mma16816(accs[nt], qfh[ks], blp);
            }
        }

        // ---- scale + causal mask ----
        const int qrow0 = q0 + wid * 16 + (lane >> 2);
        const bool diag = (k0 + 63 > q0 + wid * 16);
#pragma unroll
        for (int nt = 0; nt < 8; nt++) {
#pragma unroll
            for (int c = 0; c < 4; c++) {
                float v = accs[nt][c] * 0.125f;
                if (diag) {
                    int col = k0 + nt * 8 + 2 * (lane & 3) + (c & 1);
                    int row = qrow0 + ((c >> 1) << 3);
                    if (col > row) v = -1e30f;
                }
                accs[nt][c] = v;
            }
        }

        // ---- online softmax ----
        float mA = -1e30f, mB = -1e30f;
#pragma unroll
        for (int nt = 0; nt < 8; nt++) {
            mA = fmaxf(mA, fmaxf(accs[nt][0], accs[nt][1]));
            mB = fmaxf(mB, fmaxf(accs[nt][2], accs[nt][3]));
        }
        mA = fmaxf(mA, __shfl_xor_sync(0xffffffffu, mA, 1));
        mA = fmaxf(mA, __shfl_xor_sync(0xffffffffu, mA, 2));
        mB = fmaxf(mB, __shfl_xor_sync(0xffffffffu, mB, 1));
        mB = fmaxf(mB, __shfl_xor_sync(0xffffffffu, mB, 2));
        float mnA = fmaxf(mr0, mA), mnB = fmaxf(mr1, mB);
        float aA = __expf(mr0 - mnA), aB = __expf(mr1 - mnB);

        float psA = 0.f, psB = 0.f;
#pragma unroll
        for (int nt = 0; nt < 8; nt++) {
            accs[nt][0] = __expf(accs[nt][0] - mnA);
            accs[nt][1] = __expf(accs[nt][1] - mnA);
            accs[nt][2] = __expf(accs[nt][2] - mnB);
            accs[nt][3] = __expf(accs[nt][3] - mnB);
            psA += accs[nt][0] + accs[nt][1];
            psB += accs[nt][2] + accs[nt][3];
        }
        psA += __shfl_xor_sync(0xffffffffu, psA, 1);
        psA += __shfl_xor_sync(0xffffffffu, psA, 2);
        psB += __shfl_xor_sync(0xffffffffu, psB, 1);
        psB += __shfl_xor_sync(0xffffffffu, psB, 2);
        lr0 = lr0 * aA + psA;
        lr1 = lr1 * aB + psB;
        mr0 = mnA;
        mr1 = mnB;
#pragma unroll
        for (int nt = 0; nt < 8; nt++) {
            acc_o[nt][0] *= aA;
            acc_o[nt][1] *= aA;
            acc_o[nt][2] *= aB;
            acc_o[nt][3] *= aB;
        }

        // ---- P -> bf16 hi/lo a-fragments ----
        uint32_t pfh[4][4], pfl[4][4];
#pragma unroll
        for (int ks = 0; ks < 4; ks++) {
#pragma unroll
            for (int half = 0; half < 2; half++) {
                int nt = 2 * ks + half;
                float f0 = accs[nt][0], f1 = accs[nt][1];
                float f2 = accs[nt][2], f3 = accs[nt][3];
                __nv_bfloat16 h0 = __float2bfloat16(f0), h1 = __float2bfloat16(f1);
                __nv_bfloat16 h2 = __float2bfloat16(f2), h3 = __float2bfloat16(f3);
                pfh[ks][half * 2 + 0] = pack_bf16(__bfloat162float(h0),
                                                 __bfloat162float(h1));
                pfh[ks][half * 2 + 1] = pack_bf16(__bfloat162float(h2),
                                                 __bfloat162float(h3));
                pfl[ks][half * 2 + 0] = pack_bf16(f0 - __bfloat162float(h0),
                                                  f1 - __bfloat162float(h1));
                pfl[ks][half * 2 + 1] = pack_bf16(f2 - __bfloat162float(h2),
                                                  f3 - __bfloat162float(h3));
            }
        }

        // ---- O += P V (split x3), V frags via ldmatrix.trans ----
#pragma unroll
        for (int ks = 0; ks < 4; ks++) {
            uint32_t vfh[4][4];
#pragma unroll
            for (int j = 0; j < 4; j++) {
                int g = lane >> 3;
                int nt = 2 * j + (g >> 1);
                int kh = g & 1;
                int row = ks * 16 + kh * 8 + (lane & 7);
                uint32_t off = fswz(row, nt);
                ldm4t(vfh[j], Vb + off);
            }
#pragma unroll
            for (int nt = 0; nt < 8; nt++) {
                const uint32_t* bp = &vfh[nt >> 1][(nt & 1) * 2];
                mma16816(acc_o[nt], pfh[ks], bp);
                mma16816(acc_o[nt], pfl[ks], bp);
            }
            uint32_t vfl[4][4];
#pragma unroll
            for (int j = 0; j < 4; j++) {
                int g = lane >> 3;
                int nt = 2 * j + (g >> 1);
                int kh = g & 1;
                int row = ks * 16 + kh * 8 + (lane & 7);
                uint32_t off = fswz(row, nt);
                ldm4t(vfl[j], Vb + FA_TILE_B + off);
            }
#pragma unroll
            for (int nt = 0; nt < 8; nt++) {
                const uint32_t* bp = &vfl[nt >> 1][(nt & 1) * 2];
                mma16816(acc_o[nt], pfh[ks], bp);
            }
        }
        __syncthreads();
    }

    // ---- epilogue: normalize, split to yh/yl ----
    float invA = 1.f / lr0, invB = 1.f / lr1;
    size_t rA = (size_t)(b * TT + q0 + wid * 16 + (lane >> 2));
    size_t rB = rA + 8;
#pragma unroll
    for (int nt = 0; nt < 8; nt++) {
        int col = h * 64 + nt * 8 + 2 * (lane & 3);
        float f0 = acc_o[nt][0] * invA, f1 = acc_o[nt][1] * invA;
        float f2 = acc_o[nt][2] * invB, f3 = acc_o[nt][3] * invB;
        __nv_bfloat16 h0 = __float2bfloat16(f0), h1 = __float2bfloat16(f1);
        __nv_bfloat16 h2 = __float2bfloat16(f2), h3 = __float2bfloat16(f3);
        *(uint32_t*)(yh + rA * DD + col) =
            pack_bf16(__bfloat162float(h0), __bfloat162float(h1));
        *(uint32_t*)(yh + rB * DD + col) =
            pack_bf16(__bfloat162float(h2), __bfloat162float(h3));
        *(uint32_t*)(yl + rA * DD + col) =
            pack_bf16(f0 - __bfloat162float(h0), f1 - __bfloat162float(h1));
        *(uint32_t*)(yl + rB * DD + col) =
            pack_bf16(f2 - __bfloat162float(h2), f3 - __bfloat162float(h3));
    }
}

// ---------------------------------------------------------------------------
// Launch
// ---------------------------------------------------------------------------
extern "C" void kernel_launch(void* const* d_in, const int* in_sizes, int n_in,
                              void* d_out, int out_size)
{
    const float* x     = (const float*)d_in[0];
    const float* W_qkv = (const float*)d_in[1];
    const float* b_qkv = (const float*)d_in[2];
    const float* W_o   = (const float*)d_in[3];
    const float* b_o   = (const float*)d_in[4];
    float* out = (float*)d_out;

    __nv_bfloat16 *qkvh, *qkvl, *xh, *xl, *yh, *yl, *wqh, *wql, *woh, *wol;
    cudaGetSymbolAddress((void**)&qkvh, g_qkvh);
    cudaGetSymbolAddress((void**)&qkvl, g_qkvl);
    cudaGetSymbolAddress((void**)&xh, g_xh);
    cudaGetSymbolAddress((void**)&xl, g_xl);
    cudaGetSymbolAddress((void**)&yh, g_yh);
    cudaGetSymbolAddress((void**)&yl, g_yl);
    cudaGetSymbolAddress((void**)&wqh, g_wqh);
    cudaGetSymbolAddress((void**)&wql, g_wql);
    cudaGetSymbolAddress((void**)&woh, g_woh);
    cudaGetSymbolAddress((void**)&wol, g_wol);

    cudaFuncSetAttribute(gemm_mma<true>, cudaFuncAttributeMaxDynamicSharedMemorySize,
                         GSMEM_BYTES);
    cudaFuncSetAttribute(gemm_mma<false>, cudaFuncAttributeMaxDynamicSharedMemorySize,
                         GSMEM_BYTES);
    cudaFuncSetAttribute(flash_tc, cudaFuncAttributeMaxDynamicSharedMemorySize,
                         FA_SMEM);

    // conversions
    split_f32<<<(MM * KK / 4 + 255) / 256, 256>>>(x, xh, xl, MM * KK);
    split_transpose<<<dim3(TD3 / 32, KK / 32), dim3(32, 8)>>>(W_qkv, wqh, wql, KK, TD3);
    split_transpose<<<dim3(DD / 32, KK / 32), dim3(32, 8)>>>(W_o, woh, wol, KK, DD);

    // 1) QKV projection -> split bf16 qkv directly
    gemm_mma<true><<<dim3(TD3 / 128, MM / 128), 256, GSMEM_BYTES>>>(
        xh, xl, wqh, wql, b_qkv, nullptr, qkvh, qkvl, TD3);

    // 2) causal flash attention on tensor cores -> split y directly
    flash_tc<<<dim3(TT / 128, BB * HH), 256, FA_SMEM>>>(qkvh, qkvl, yh, yl);

    // 3) output projection -> fp32 out
    gemm_mma<false><<<dim3(DD / 128, MM / 128), 256, GSMEM_BYTES>>>(
        yh, yl, woh, wol, b_o, out, nullptr, nullptr, DD);
}

// round 6
// speedup vs baseline: 4.6655x; 1.0232x over previous
#include <cuda_runtime.h>
#include <cuda_bf16.h>
#include <cstdint>

// Problem constants (fixed by the reference)
#define BB 2
#define TT 2048
#define DD 1024
#define HH 16
#define DKK 64
#define TD3 3072    // 3*D
#define MM (BB*TT)  // 4096 rows
#define KK 1024     // GEMM K for both projections

// ---------------------------------------------------------------------------
// Scratch (allocation-free rule: __device__ globals)
// ---------------------------------------------------------------------------
__device__ __nv_bfloat16 g_qkvh[MM * TD3];   // 24 MB  qkv hi
__device__ __nv_bfloat16 g_qkvl[MM * TD3];   // 24 MB  qkv lo
__device__ __nv_bfloat16 g_xh[MM * KK];
__device__ __nv_bfloat16 g_xl[MM * KK];
__device__ __nv_bfloat16 g_yh[MM * KK];      // attention out hi
__device__ __nv_bfloat16 g_yl[MM * KK];      // attention out lo
__device__ __nv_bfloat16 g_wqh[TD3 * KK];    // W_qkv^T split, [N][K]
__device__ __nv_bfloat16 g_wql[TD3 * KK];
__device__ __nv_bfloat16 g_woh[DD * KK];     // W_o^T split
__device__ __nv_bfloat16 g_wol[DD * KK];

// ---------------------------------------------------------------------------
// PTX helpers (plain sm_100-legal: cp.async + ldmatrix + mma.sync)
// ---------------------------------------------------------------------------
__device__ __forceinline__ uint32_t smem_u32(const void* p) {
    uint32_t a;
    asm("{ .reg .u64 t; cvta.to.shared.u64 t, %1; cvt.u32.u64 %0, t; }"
        : "=r"(a) : "l"(p));
    return a;
}
__device__ __forceinline__ void cp16(uint32_t dst, const void* src) {
    asm volatile("cp.async.cg.shared.global [%0], [%1], 16;" :: "r"(dst), "l"(src));
}
__device__ __forceinline__ void cp_commit() {
    asm volatile("cp.async.commit_group;" ::: "memory");
}
template <int N>
__device__ __forceinline__ void cp_wait() {
    asm volatile("cp.async.wait_group %0;" :: "n"(N) : "memory");
}
__device__ __forceinline__ void ldm4(uint32_t* r, uint32_t addr) {
    asm volatile("ldmatrix.sync.aligned.m8n8.x4.shared.b16 {%0,%1,%2,%3}, [%4];"
                 : "=r"(r[0]), "=r"(r[1]), "=r"(r[2]), "=r"(r[3]) : "r"(addr));
}
__device__ __forceinline__ void ldm4t(uint32_t* r, uint32_t addr) {
    asm volatile("ldmatrix.sync.aligned.m8n8.x4.trans.shared.b16 {%0,%1,%2,%3}, [%4];"
                 : "=r"(r[0]), "=r"(r[1]), "=r"(r[2]), "=r"(r[3]) : "r"(addr));
}
__device__ __forceinline__ void mma16816(float* c, const uint32_t* a,
                                         const uint32_t* b) {
    asm volatile(
        "mma.sync.aligned.m16n8k16.row.col.f32.bf16.bf16.f32 "
        "{%0,%1,%2,%3}, {%4,%5,%6,%7}, {%8,%9}, {%0,%1,%2,%3};"
        : "+f"(c[0]), "+f"(c[1]), "+f"(c[2]), "+f"(c[3])
        : "r"(a[0]), "r"(a[1]), "r"(a[2]), "r"(a[3]), "r"(b[0]), "r"(b[1]));
}
__device__ __forceinline__ uint32_t pack_bf16(float a, float b) {
    __nv_bfloat162 t = __floats2bfloat162_rn(a, b);  // .x = a (low)
    return *(uint32_t*)&t;
}

// ---------------------------------------------------------------------------
// Conversion kernels: fp32 -> (hi, lo) bf16 split
// ---------------------------------------------------------------------------
struct __align__(8) bf4 { __nv_bfloat16 v[4]; };

__global__ __launch_bounds__(256) void split_f32(
    const float* __restrict__ src, __nv_bfloat16* __restrict__ hi,
    __nv_bfloat16* __restrict__ lo, int n)
{
    int i = (blockIdx.x * blockDim.x + threadIdx.x) * 4;
    if (i >= n) return;
    float4 v = *(const float4*)(src + i);
    bf4 h, l;
    float vv[4] = {v.x, v.y, v.z, v.w};
#pragma unroll
    for (int j = 0; j < 4; j++) {
        __nv_bfloat16 a = __float2bfloat16(vv[j]);
        h.v[j] = a;
        l.v[j] = __float2bfloat16(vv[j] - __bfloat162float(a));
    }
    *(bf4*)(hi + i) = h;
    *(bf4*)(lo + i) = l;
}

// W [K][N] fp32 -> Wt_hi/lo [N][K] bf16 (transpose + split)
__global__ __launch_bounds__(256) void split_transpose(
    const float* __restrict__ W, __nv_bfloat16* __restrict__ Thi,
    __nv_bfloat16* __restrict__ Tlo, int K, int N)
{
    __shared__ float t[32][33];
    int n0 = blockIdx.x * 32, k0 = blockIdx.y * 32;
    int tx = threadIdx.x, ty = threadIdx.y;
#pragma unroll
    for (int i = ty; i < 32; i += 8)
        t[i][tx] = W[(size_t)(k0 + i) * N + n0 + tx];
    __syncthreads();
#pragma unroll
    for (int i = ty; i < 32; i += 8) {
        float v = t[tx][i];
        __nv_bfloat16 h = __float2bfloat16(v);
        Thi[(size_t)(n0 + i) * K + k0 + tx] = h;
        Tlo[(size_t)(n0 + i) * K + k0 + tx] =
            __float2bfloat16(v - __bfloat162float(h));
    }
}

// ---------------------------------------------------------------------------
// mma.sync GEMM (split-bf16 x3). 3-stage cp.async pipeline, one
// __syncthreads per chunk, 3-pass MMA term ordering.
// ---------------------------------------------------------------------------
#define TILE_B 8192                    // 128 rows * 64 B
#define STAGE_B (4 * TILE_B)           // Ahi, Alo, Bhi, Blo
#define GSTAGES 3
#define GSMEM_BYTES (GSTAGES * STAGE_B)  // 98304
#define NCHUNK (KK / 32)               // 32

__device__ __forceinline__ uint32_t swz_off(int row, int chunk) {
    return (uint32_t)(row * 64 + ((chunk ^ ((row >> 1) & 3)) << 4));
}

__device__ __forceinline__ void load_stage(
    uint32_t sb, int s, int k0,
    const __nv_bfloat16* __restrict__ Ahi, const __nv_bfloat16* __restrict__ Alo,
    const __nv_bfloat16* __restrict__ Bhi, const __nv_bfloat16* __restrict__ Blo,
    int m0, int n0, int tid)
{
    uint32_t base = sb + (uint32_t)s * STAGE_B;
    const __nv_bfloat16* srcs[4] = {Ahi, Alo, Bhi, Blo};
    int r0s[4] = {m0, m0, n0, n0};
#pragma unroll
    for (int t = 0; t < 4; t++) {
        const __nv_bfloat16* p = srcs[t];
        int r0 = r0s[t];
        uint32_t tb = base + t * TILE_B;
#pragma unroll
        for (int i = 0; i < 2; i++) {
            int c = tid + i * 256;
            int row = c >> 2;
            int ch = c & 3;
            const void* g = p + (size_t)(r0 + row) * KK + k0 + ch * 8;
            cp16(tb + swz_off(row, ch), g);
        }
    }
    cp_commit();
}

template <bool SPLIT_OUT>
__global__ __launch_bounds__(256, 2) void gemm_mma(
    const __nv_bfloat16* __restrict__ Ahi, const __nv_bfloat16* __restrict__ Alo,
    const __nv_bfloat16* __restrict__ Bhi, const __nv_bfloat16* __restrict__ Blo,
    const float* __restrict__ bias, float* __restrict__ C,
    __nv_bfloat16* __restrict__ Ch, __nv_bfloat16* __restrict__ Cl, int N)
{
    extern __shared__ char smem[];
    uint32_t sb = smem_u32(smem);
    const int tid = threadIdx.x;
    const int wid = tid >> 5;
    const int lane = tid & 31;
    const int warp_m = wid >> 1;
    const int warp_n = wid & 1;
    const int n0 = blockIdx.x * 128;
    const int m0 = blockIdx.y * 128;

    float acc[2][8][4];
#pragma unroll
    for (int i = 0; i < 2; i++)
#pragma unroll
        for (int j = 0; j < 8; j++)
#pragma unroll
            for (int k = 0; k < 4; k++) acc[i][j][k] = 0.f;

    // Prologue: stages 0 and 1 in flight (one commit group each)
    load_stage(sb, 0, 0, Ahi, Alo, Bhi, Blo, m0, n0, tid);
    load_stage(sb, 1, 32, Ahi, Alo, Bhi, Blo, m0, n0, tid);

    for (int c = 0; c < NCHUNK; c++) {
        // stage c ready (groups pending: {c, c+1} except last iter {c})
        if (c == NCHUNK - 1) cp_wait<0>(); else cp_wait<1>();
        __syncthreads();
        // Issue load for c+2 into buffer ((c+2)%3) == buffer of c-1.
        // Safe: every warp computed chunk c-1 before this barrier.
        if (c + 2 < NCHUNK)
            load_stage(sb, (c + 2) % GSTAGES, (c + 2) * 32,
                       Ahi, Alo, Bhi, Blo, m0, n0, tid);

        uint32_t abase = sb + (uint32_t)(c % GSTAGES) * STAGE_B;
#pragma unroll
        for (int ks = 0; ks < 2; ks++) {
            uint32_t ah[2][4], al[2][4], bh[4][4], bl[4][4];
#pragma unroll
            for (int mt = 0; mt < 2; mt++) {
                int row = warp_m * 32 + mt * 16 + (lane & 15);
                int ch = ks * 2 + (lane >> 4);
                uint32_t off = swz_off(row, ch);
                ldm4(ah[mt], abase + off);
                ldm4(al[mt], abase + TILE_B + off);
            }
#pragma unroll
            for (int p = 0; p < 4; p++) {
                int row = warp_n * 64 + (p * 2 + (lane >> 4)) * 8 + (lane & 7);
                int ch = ks * 2 + ((lane >> 3) & 1);
                uint32_t off = swz_off(row, ch);
                ldm4(bh[p], abase + 2 * TILE_B + off);
                ldm4(bl[p], abase + 3 * TILE_B + off);
            }
            // 3 passes over all 16 accumulators: reuse distance 16 MMAs
#pragma unroll
            for (int mt = 0; mt < 2; mt++)
#pragma unroll
                for (int nt = 0; nt < 8; nt++)
                    mma16816(acc[mt][nt], ah[mt], &bh[nt >> 1][(nt & 1) * 2]);
#pragma unroll
            for (int mt = 0; mt < 2; mt++)
#pragma unroll
                for (int nt = 0; nt < 8; nt++)
                    mma16816(acc[mt][nt], al[mt], &bh[nt >> 1][(nt & 1) * 2]);
#pragma unroll
            for (int mt = 0; mt < 2; mt++)
#pragma unroll
                for (int nt = 0; nt < 8; nt++)
                    mma16816(acc[mt][nt], ah[mt], &bl[nt >> 1][(nt & 1) * 2]);
        }
        // no trailing barrier: next iteration's barrier provides WAR safety
    }

#pragma unroll
    for (int mt = 0; mt < 2; mt++) {
        int m = m0 + warp_m * 32 + mt * 16 + (lane >> 2);
#pragma unroll
        for (int nt = 0; nt < 8; nt++) {
            int n = n0 + warp_n * 64 + nt * 8 + (lane & 3) * 2;
            float b0 = bias[n], b1 = bias[n + 1];
            float f0 = acc[mt][nt][0] + b0, f1 = acc[mt][nt][1] + b1;
            float f2 = acc[mt][nt][2] + b0, f3 = acc[mt][nt][3] + b1;
            if (SPLIT_OUT) {
                __nv_bfloat16 h0 = __float2bfloat16(f0), h1 = __float2bfloat16(f1);
                __nv_bfloat16 h2 = __float2bfloat16(f2), h3 = __float2bfloat16(f3);
                uint32_t hp0 = pack_bf16(__bfloat162float(h0), __bfloat162float(h1));
                uint32_t hp1 = pack_bf16(__bfloat162float(h2), __bfloat162float(h3));
                uint32_t lp0 = pack_bf16(f0 - __bfloat162float(h0),
                                         f1 - __bfloat162float(h1));
                uint32_t lp1 = pack_bf16(f2 - __bfloat162float(h2),
                                         f3 - __bfloat162float(h3));
                *(uint32_t*)(Ch + (size_t)m * N + n) = hp0;
                *(uint32_t*)(Ch + (size_t)(m + 8) * N + n) = hp1;
                *(uint32_t*)(Cl + (size_t)m * N + n) = lp0;
                *(uint32_t*)(Cl + (size_t)(m + 8) * N + n) = lp1;
            } else {
                float2 o0 = {f0, f1}, o1 = {f2, f3};
                *(float2*)(C + (size_t)m * N + n) = o0;
                *(float2*)(C + (size_t)(m + 8) * N + n) = o1;
            }
        }
    }
}

// ---------------------------------------------------------------------------
// Tensor-core flash attention (causal). BM=128 (8 warps x m16), BN=64,
// split-bf16 x3 for QK^T and PV. 2-stage cp.async, ONE sync per tile.
// ---------------------------------------------------------------------------
#define FA_TILE_B 8192                  // 64 rows * 128 B
#define FA_STAGE_B (4 * FA_TILE_B)      // Kh, Kl, Vh, Vl
#define FA_SMEM (2 * FA_STAGE_B)        // 65536

__device__ __forceinline__ uint32_t fswz(int row, int ch) {
    return (uint32_t)(row * 128 + ((ch ^ (row & 7)) << 4));
}

__device__ __forceinline__ void fa_load(
    uint32_t sb, int s, int k0,
    const __nv_bfloat16* __restrict__ qh, const __nv_bfloat16* __restrict__ ql,
    int b, int h, int tid)
{
    uint32_t base = sb + (uint32_t)s * FA_STAGE_B;
    const __nv_bfloat16* ptrs[4] = {qh, ql, qh, ql};
    int goff[4] = {1024, 1024, 2048, 2048};   // K hi/lo, V hi/lo
#pragma unroll
    for (int t = 0; t < 4; t++) {
        const __nv_bfloat16* p = ptrs[t];
        uint32_t tb = base + t * FA_TILE_B;
#pragma unroll
        for (int i = 0; i < 2; i++) {
            int idx = tid + i * 256;
            int row = idx >> 3;
            int ch = idx & 7;
            const void* g = p + (size_t)(b * TT + k0 + row) * TD3 + goff[t]
                          + h * 64 + ch * 8;
            cp16(tb + fswz(row, ch), g);
        }
    }
    cp_commit();
}

__global__ __launch_bounds__(256, 1) void flash_tc(
    const __nv_bfloat16* __restrict__ qkvh, const __nv_bfloat16* __restrict__ qkvl,
    __nv_bfloat16* __restrict__ yh, __nv_bfloat16* __restrict__ yl)
{
    extern __shared__ char smem[];
    uint32_t sb = smem_u32(smem);
    const int tid = threadIdx.x;
    const int wid = tid >> 5;
    const int lane = tid & 31;
    const int qt = (int)gridDim.x - 1 - (int)blockIdx.x;   // big tiles first
    const int bh = blockIdx.y;
    const int b = bh >> 4;
    const int h = bh & 15;
    const int q0 = qt * 128;

    const int ntile = 2 * (qt + 1);
    fa_load(sb, 0, 0, qkvh, qkvl, b, h, tid);   // 1 group in flight

    // ---- Q fragments (hi/lo) straight from gmem (overlaps with cp.async) ----
    uint32_t qfh[4][4], qfl[4][4];
    {
        size_t r0g = (size_t)(b * TT + q0 + wid * 16 + (lane >> 2));
        const uint32_t* p0h = (const uint32_t*)(qkvh + r0g * TD3 + h * 64);
        const uint32_t* p1h = (const uint32_t*)(qkvh + (r0g + 8) * TD3 + h * 64);
        const uint32_t* p0l = (const uint32_t*)(qkvl + r0g * TD3 + h * 64);
        const uint32_t* p1l = (const uint32_t*)(qkvl + (r0g + 8) * TD3 + h * 64);
        int c2 = lane & 3;
#pragma unroll
        for (int ks = 0; ks < 4; ks++) {
            qfh[ks][0] = p0h[ks * 8 + c2];
            qfh[ks][1] = p1h[ks * 8 + c2];
            qfh[ks][2] = p0h[ks * 8 + c2 + 4];
            qfh[ks][3] = p1h[ks * 8 + c2 + 4];
            qfl[ks][0] = p0l[ks * 8 + c2];
            qfl[ks][1] = p1l[ks * 8 + c2];
            qfl[ks][2] = p0l[ks * 8 + c2 + 4];
            qfl[ks][3] = p1l[ks * 8 + c2 + 4];
        }
    }

    float acc_o[8][4];
#pragma unroll
    for (int i = 0; i < 8; i++)
#pragma unroll
        for (int j = 0; j < 4; j++) acc_o[i][j] = 0.f;
    float mr0 = -1e30f, mr1 = -1e30f, lr0 = 0.f, lr1 = 0.f;

    for (int kt = 0; kt < ntile; kt++) {
        const int s = kt & 1;
        const int k0 = kt * 64;
        cp_wait<0>();          // tile kt resident (issued >=1 tile ago)
        __syncthreads();
        // Prefetch kt+1 into the other stage (overwrites kt-1: all warps
        // finished computing it before this barrier).
        if (kt + 1 < ntile)
            fa_load(sb, s ^ 1, (kt + 1) * 64, qkvh, qkvl, b, h, tid);

        uint32_t Kb = sb + (uint32_t)s * FA_STAGE_B;
        uint32_t Vb = Kb + 2 * FA_TILE_B;

        // ---- S = Q K^T (split x3, 3-pass ordering) ----
        float accs[8][4];
#pragma unroll
        for (int i = 0; i < 8; i++)
#pragma unroll
            for (int j = 0; j < 4; j++) accs[i][j] = 0.f;

#pragma unroll
        for (int ks = 0; ks < 4; ks++) {
            uint32_t kfh[4][4], kfl[4][4];
#pragma unroll
            for (int j = 0; j < 4; j++) {
                int g = lane >> 3;
                int nt = 2 * j + (g >> 1);
                int kh = g & 1;
                int row = nt * 8 + (lane & 7);
                uint32_t off = fswz(row, ks * 2 + kh);
                ldm4(kfh[j], Kb + off);
                ldm4(kfl[j], Kb + FA_TILE_B + off);
            }
#pragma unroll
            for (int nt = 0; nt < 8; nt++)
                mma16816(accs[nt], qfh[ks], &kfh[nt >> 1][(nt & 1) * 2]);
#pragma unroll
            for (int nt = 0; nt < 8; nt++)
                mma16816(accs[nt], qfl[ks], &kfh[nt >> 1][(nt & 1) * 2]);
#pragma unroll
            for (int nt = 0; nt < 8; nt++)
                mma16816(accs[nt], qfh[ks], &kfl[nt >> 1][(nt & 1) * 2]);
        }

        // ---- scale + causal mask ----
        const int qrow0 = q0 + wid * 16 + (lane >> 2);
        const bool diag = (k0 + 63 > q0 + wid * 16);
#pragma unroll
        for (int nt = 0; nt < 8; nt++) {
#pragma unroll
            for (int c = 0; c < 4; c++) {
                float v = accs[nt][c] * 0.125f;
                if (diag) {
                    int col = k0 + nt * 8 + 2 * (lane & 3) + (c & 1);
                    int row = qrow0 + ((c >> 1) << 3);
                    if (col > row) v = -1e30f;
                }
                accs[nt][c] = v;
            }
        }

        // ---- online softmax ----
        float mA = -1e30f, mB = -1e30f;
#pragma unroll
        for (int nt = 0; nt < 8; nt++) {
            mA = fmaxf(mA, fmaxf(accs[nt][0], accs[nt][1]));
            mB = fmaxf(mB, fmaxf(accs[nt][2], accs[nt][3]));
        }
        mA = fmaxf(mA, __shfl_xor_sync(0xffffffffu, mA, 1));
        mA = fmaxf(mA, __shfl_xor_sync(0xffffffffu, mA, 2));
        mB = fmaxf(mB, __shfl_xor_sync(0xffffffffu, mB, 1));
        mB = fmaxf(mB, __shfl_xor_sync(0xffffffffu, mB, 2));
        float mnA = fmaxf(mr0, mA), mnB = fmaxf(mr1, mB);
        float aA = __expf(mr0 - mnA), aB = __expf(mr1 - mnB);

        float psA = 0.f, psB = 0.f;
#pragma unroll
        for (int nt = 0; nt < 8; nt++) {
            accs[nt][0] = __expf(accs[nt][0] - mnA);
            accs[nt][1] = __expf(accs[nt][1] - mnA);
            accs[nt][2] = __expf(accs[nt][2] - mnB);
            accs[nt][3] = __expf(accs[nt][3] - mnB);
            psA += accs[nt][0] + accs[nt][1];
            psB += accs[nt][2] + accs[nt][3];
        }
        psA += __shfl_xor_sync(0xffffffffu, psA, 1);
        psA += __shfl_xor_sync(0xffffffffu, psA, 2);
        psB += __shfl_xor_sync(0xffffffffu, psB, 1);
        psB += __shfl_xor_sync(0xffffffffu, psB, 2);
        lr0 = lr0 * aA + psA;
        lr1 = lr1 * aB + psB;
        mr0 = mnA;
        mr1 = mnB;
#pragma unroll
        for (int nt = 0; nt < 8; nt++) {
            acc_o[nt][0] *= aA;
            acc_o[nt][1] *= aA;
            acc_o[nt][2] *= aB;
            acc_o[nt][3] *= aB;
        }

        // ---- P -> bf16 hi/lo a-fragments ----
        uint32_t pfh[4][4], pfl[4][4];
#pragma unroll
        for (int ks = 0; ks < 4; ks++) {
#pragma unroll
            for (int half = 0; half < 2; half++) {
                int nt = 2 * ks + half;
                float f0 = accs[nt][0], f1 = accs[nt][1];
                float f2 = accs[nt][2], f3 = accs[nt][3];
                __nv_bfloat16 h0 = __float2bfloat16(f0), h1 = __float2bfloat16(f1);
                __nv_bfloat16 h2 = __float2bfloat16(f2), h3 = __float2bfloat16(f3);
                pfh[ks][half * 2 + 0] = pack_bf16(__bfloat162float(h0),
                                                 __bfloat162float(h1));
                pfh[ks][half * 2 + 1] = pack_bf16(__bfloat162float(h2),
                                                 __bfloat162float(h3));
                pfl[ks][half * 2 + 0] = pack_bf16(f0 - __bfloat162float(h0),
                                                  f1 - __bfloat162float(h1));
                pfl[ks][half * 2 + 1] = pack_bf16(f2 - __bfloat162float(h2),
                                                  f3 - __bfloat162float(h3));
            }
        }

        // ---- O += P V (split x3), V frags via ldmatrix.trans ----
#pragma unroll
        for (int ks = 0; ks < 4; ks++) {
            uint32_t vfh[4][4];
#pragma unroll
            for (int j = 0; j < 4; j++) {
                int g = lane >> 3;
                int nt = 2 * j + (g >> 1);
                int kh = g & 1;
                int row = ks * 16 + kh * 8 + (lane & 7);
                uint32_t off = fswz(row, nt);
                ldm4t(vfh[j], Vb + off);
            }
#pragma unroll
            for (int nt = 0; nt < 8; nt++) {
                const uint32_t* bp = &vfh[nt >> 1][(nt & 1) * 2];
                mma16816(acc_o[nt], pfh[ks], bp);
                mma16816(acc_o[nt], pfl[ks], bp);
            }
            uint32_t vfl[4][4];
#pragma unroll
            for (int j = 0; j < 4; j++) {
                int g = lane >> 3;
                int nt = 2 * j + (g >> 1);
                int kh = g & 1;
                int row = ks * 16 + kh * 8 + (lane & 7);
                uint32_t off = fswz(row, nt);
                ldm4t(vfl[j], Vb + FA_TILE_B + off);
            }
#pragma unroll
            for (int nt = 0; nt < 8; nt++) {
                const uint32_t* bp = &vfl[nt >> 1][(nt & 1) * 2];
                mma16816(acc_o[nt], pfh[ks], bp);
            }
        }
        // no trailing barrier: next iteration's barrier provides WAR safety
    }

    // ---- epilogue: normalize, split to yh/yl ----
    float invA = 1.f / lr0, invB = 1.f / lr1;
    size_t rA = (size_t)(b * TT + q0 + wid * 16 + (lane >> 2));
    size_t rB = rA + 8;
#pragma unroll
    for (int nt = 0; nt < 8; nt++) {
        int col = h * 64 + nt * 8 + 2 * (lane & 3);
        float f0 = acc_o[nt][0] * invA, f1 = acc_o[nt][1] * invA;
        float f2 = acc_o[nt][2] * invB, f3 = acc_o[nt][3] * invB;
        __nv_bfloat16 h0 = __float2bfloat16(f0), h1 = __float2bfloat16(f1);
        __nv_bfloat16 h2 = __float2bfloat16(f2), h3 = __float2bfloat16(f3);
        *(uint32_t*)(yh + rA * DD + col) =
            pack_bf16(__bfloat162float(h0), __bfloat162float(h1));
        *(uint32_t*)(yh + rB * DD + col) =
            pack_bf16(__bfloat162float(h2), __bfloat162float(h3));
        *(uint32_t*)(yl + rA * DD + col) =
            pack_bf16(f0 - __bfloat162float(h0), f1 - __bfloat162float(h1));
        *(uint32_t*)(yl + rB * DD + col) =
            pack_bf16(f2 - __bfloat162float(h2), f3 - __bfloat162float(h3));
    }
}

// ---------------------------------------------------------------------------
// Launch
// ---------------------------------------------------------------------------
extern "C" void kernel_launch(void* const* d_in, const int* in_sizes, int n_in,
                              void* d_out, int out_size)
{
    const float* x     = (const float*)d_in[0];
    const float* W_qkv = (const float*)d_in[1];
    const float* b_qkv = (const float*)d_in[2];
    const float* W_o   = (const float*)d_in[3];
    const float* b_o   = (const float*)d_in[4];
    float* out = (float*)d_out;

    __nv_bfloat16 *qkvh, *qkvl, *xh, *xl, *yh, *yl, *wqh, *wql, *woh, *wol;
    cudaGetSymbolAddress((void**)&qkvh, g_qkvh);
    cudaGetSymbolAddress((void**)&qkvl, g_qkvl);
    cudaGetSymbolAddress((void**)&xh, g_xh);
    cudaGetSymbolAddress((void**)&xl, g_xl);
    cudaGetSymbolAddress((void**)&yh, g_yh);
    cudaGetSymbolAddress((void**)&yl, g_yl);
    cudaGetSymbolAddress((void**)&wqh, g_wqh);
    cudaGetSymbolAddress((void**)&wql, g_wql);
    cudaGetSymbolAddress((void**)&woh, g_woh);
    cudaGetSymbolAddress((void**)&wol, g_wol);

    cudaFuncSetAttribute(gemm_mma<true>, cudaFuncAttributeMaxDynamicSharedMemorySize,
                         GSMEM_BYTES);
    cudaFuncSetAttribute(gemm_mma<false>, cudaFuncAttributeMaxDynamicSharedMemorySize,
                         GSMEM_BYTES);
    cudaFuncSetAttribute(flash_tc, cudaFuncAttributeMaxDynamicSharedMemorySize,
                         FA_SMEM);

    // conversions
    split_f32<<<(MM * KK / 4 + 255) / 256, 256>>>(x, xh, xl, MM * KK);
    split_transpose<<<dim3(TD3 / 32, KK / 32), dim3(32, 8)>>>(W_qkv, wqh, wql, KK, TD3);
    split_transpose<<<dim3(DD / 32, KK / 32), dim3(32, 8)>>>(W_o, woh, wol, KK, DD);

    // 1) QKV projection -> split bf16 qkv directly
    gemm_mma<true><<<dim3(TD3 / 128, MM / 128), 256, GSMEM_BYTES>>>(
        xh, xl, wqh, wql, b_qkv, nullptr, qkvh, qkvl, TD3);

    // 2) causal flash attention on tensor cores -> split y directly
    flash_tc<<<dim3(TT / 128, BB * HH), 256, FA_SMEM>>>(qkvh, qkvl, yh, yl);

    // 3) output projection -> fp32 out
    gemm_mma<false><<<dim3(DD / 128, MM / 128), 256, GSMEM_BYTES>>>(
        yh, yl, woh, wol, b_o, out, nullptr, nullptr, DD);
}

// round 7
// speedup vs baseline: 5.6508x; 1.2112x over previous
#include <cuda_runtime.h>
#include <cuda_bf16.h>
#include <cuda_fp16.h>
#include <cstdint>

// Problem constants (fixed by the reference)
#define BB 2
#define TT 2048
#define DD 1024
#define HH 16
#define DKK 64
#define TD3 3072    // 3*D
#define MM (BB*TT)  // 4096 rows
#define KK 1024     // GEMM K for both projections

// ---------------------------------------------------------------------------
// Scratch (allocation-free rule: __device__ globals)
// ---------------------------------------------------------------------------
__device__ __nv_bfloat16 g_qkvh[MM * TD3];   // qkv hi (bf16, flash input)
__device__ __nv_bfloat16 g_qkvl[MM * TD3];   // qkv lo
__device__ __half g_xh[MM * KK];             // x split (fp16) for QKV GEMM
__device__ __half g_xl[MM * KK];
__device__ __half g_yh[MM * KK];             // attention out split (fp16)
__device__ __half g_yl[MM * KK];
__device__ __half g_wqh[TD3 * KK];           // W_qkv^T fp16, [N][K]
__device__ __half g_woh[DD * KK];            // W_o^T fp16, [N][K]

// ---------------------------------------------------------------------------
// PTX helpers (plain sm_100-legal: cp.async + ldmatrix + mma.sync)
// ---------------------------------------------------------------------------
__device__ __forceinline__ uint32_t smem_u32(const void* p) {
    uint32_t a;
    asm("{ .reg .u64 t; cvta.to.shared.u64 t, %1; cvt.u32.u64 %0, t; }"
        : "=r"(a) : "l"(p));
    return a;
}
__device__ __forceinline__ void cp16(uint32_t dst, const void* src) {
    asm volatile("cp.async.cg.shared.global [%0], [%1], 16;" :: "r"(dst), "l"(src));
}
__device__ __forceinline__ void cp_commit() {
    asm volatile("cp.async.commit_group;" ::: "memory");
}
template <int N>
__device__ __forceinline__ void cp_wait() {
    asm volatile("cp.async.wait_group %0;" :: "n"(N) : "memory");
}
__device__ __forceinline__ void ldm4(uint32_t* r, uint32_t addr) {
    asm volatile("ldmatrix.sync.aligned.m8n8.x4.shared.b16 {%0,%1,%2,%3}, [%4];"
                 : "=r"(r[0]), "=r"(r[1]), "=r"(r[2]), "=r"(r[3]) : "r"(addr));
}
__device__ __forceinline__ void ldm4t(uint32_t* r, uint32_t addr) {
    asm volatile("ldmatrix.sync.aligned.m8n8.x4.trans.shared.b16 {%0,%1,%2,%3}, [%4];"
                 : "=r"(r[0]), "=r"(r[1]), "=r"(r[2]), "=r"(r[3]) : "r"(addr));
}
// bf16 MMA (flash)
__device__ __forceinline__ void mma16816(float* c, const uint32_t* a,
                                         const uint32_t* b) {
    asm volatile(
        "mma.sync.aligned.m16n8k16.row.col.f32.bf16.bf16.f32 "
        "{%0,%1,%2,%3}, {%4,%5,%6,%7}, {%8,%9}, {%0,%1,%2,%3};"
        : "+f"(c[0]), "+f"(c[1]), "+f"(c[2]), "+f"(c[3])
        : "r"(a[0]), "r"(a[1]), "r"(a[2]), "r"(a[3]), "r"(b[0]), "r"(b[1]));
}
// fp16 MMA (projection GEMMs)
__device__ __forceinline__ void mma16816h(float* c, const uint32_t* a,
                                          const uint32_t* b) {
    asm volatile(
        "mma.sync.aligned.m16n8k16.row.col.f32.f16.f16.f32 "
        "{%0,%1,%2,%3}, {%4,%5,%6,%7}, {%8,%9}, {%0,%1,%2,%3};"
        : "+f"(c[0]), "+f"(c[1]), "+f"(c[2]), "+f"(c[3])
        : "r"(a[0]), "r"(a[1]), "r"(a[2]), "r"(a[3]), "r"(b[0]), "r"(b[1]));
}
__device__ __forceinline__ uint32_t pack_bf16(float a, float b) {
    __nv_bfloat162 t = __floats2bfloat162_rn(a, b);  // .x = a (low)
    return *(uint32_t*)&t;
}
__device__ __forceinline__ uint32_t pack_half(float a, float b) {
    __half2 t = __floats2half2_rn(a, b);             // .x = a (low)
    return *(uint32_t*)&t;
}

// ---------------------------------------------------------------------------
// Conversion kernels
// ---------------------------------------------------------------------------
struct __align__(8) h4 { __half v[4]; };

// fp32 -> (hi, lo) fp16 split
__global__ __launch_bounds__(256) void split_f32h(
    const float* __restrict__ src, __half* __restrict__ hi,
    __half* __restrict__ lo, int n)
{
    int i = (blockIdx.x * blockDim.x + threadIdx.x) * 4;
    if (i >= n) return;
    float4 v = *(const float4*)(src + i);
    h4 h, l;
    float vv[4] = {v.x, v.y, v.z, v.w};
#pragma unroll
    for (int j = 0; j < 4; j++) {
        __half a = __float2half_rn(vv[j]);
        h.v[j] = a;
        l.v[j] = __float2half_rn(vv[j] - __half2float(a));
    }
    *(h4*)(hi + i) = h;
    *(h4*)(lo + i) = l;
}

// W [K][N] fp32 -> Wt [N][K] fp16 (transpose, hi only)
__global__ __launch_bounds__(256) void transpose_h(
    const float* __restrict__ W, __half* __restrict__ T, int K, int N)
{
    __shared__ float t[32][33];
    int n0 = blockIdx.x * 32, k0 = blockIdx.y * 32;
    int tx = threadIdx.x, ty = threadIdx.y;
#pragma unroll
    for (int i = ty; i < 32; i += 8)
        t[i][tx] = W[(size_t)(k0 + i) * N + n0 + tx];
    __syncthreads();
#pragma unroll
    for (int i = ty; i < 32; i += 8)
        T[(size_t)(n0 + i) * K + k0 + tx] = __float2half_rn(t[tx][i]);
}

// ---------------------------------------------------------------------------
// fp16 2-term GEMM: C = (Ah+Al) @ Bh^T + bias.  A split fp16, B single fp16.
// 128x128 tile / CTA, BK=32, 3-stage cp.async, one sync per chunk.
// ---------------------------------------------------------------------------
#define TILE_B 8192                    // 128 rows * 64 B
#define STAGE_B (3 * TILE_B)           // Ahi, Alo, Bh
#define GSTAGES 3
#define GSMEM_BYTES (GSTAGES * STAGE_B)  // 73728
#define NCHUNK (KK / 32)               // 32

__device__ __forceinline__ uint32_t swz_off(int row, int chunk) {
    return (uint32_t)(row * 64 + ((chunk ^ ((row >> 1) & 3)) << 4));
}

__device__ __forceinline__ void load_stage(
    uint32_t sb, int s, int k0,
    const __half* __restrict__ Ahi, const __half* __restrict__ Alo,
    const __half* __restrict__ Bh, int m0, int n0, int tid)
{
    uint32_t base = sb + (uint32_t)s * STAGE_B;
    const __half* srcs[3] = {Ahi, Alo, Bh};
    int r0s[3] = {m0, m0, n0};
#pragma unroll
    for (int t = 0; t < 3; t++) {
        const __half* p = srcs[t];
        int r0 = r0s[t];
        uint32_t tb = base + t * TILE_B;
#pragma unroll
        for (int i = 0; i < 2; i++) {
            int c = tid + i * 256;
            int row = c >> 2;
            int ch = c & 3;
            const void* g = p + (size_t)(r0 + row) * KK + k0 + ch * 8;
            cp16(tb + swz_off(row, ch), g);
        }
    }
    cp_commit();
}

template <bool SPLIT_OUT>
__global__ __launch_bounds__(256, 2) void gemm_mma(
    const __half* __restrict__ Ahi, const __half* __restrict__ Alo,
    const __half* __restrict__ Bh,
    const float* __restrict__ bias, float* __restrict__ C,
    __nv_bfloat16* __restrict__ Ch, __nv_bfloat16* __restrict__ Cl, int N)
{
    extern __shared__ char smem[];
    uint32_t sb = smem_u32(smem);
    const int tid = threadIdx.x;
    const int wid = tid >> 5;
    const int lane = tid & 31;
    const int warp_m = wid >> 1;
    const int warp_n = wid & 1;
    const int n0 = blockIdx.x * 128;
    const int m0 = blockIdx.y * 128;

    float acc[2][8][4];
#pragma unroll
    for (int i = 0; i < 2; i++)
#pragma unroll
        for (int j = 0; j < 8; j++)
#pragma unroll
            for (int k = 0; k < 4; k++) acc[i][j][k] = 0.f;

    load_stage(sb, 0, 0, Ahi, Alo, Bh, m0, n0, tid);
    load_stage(sb, 1, 32, Ahi, Alo, Bh, m0, n0, tid);

    for (int c = 0; c < NCHUNK; c++) {
        if (c == NCHUNK - 1) cp_wait<0>(); else cp_wait<1>();
        __syncthreads();
        // load c+2 into buffer of c-1 (all warps finished it before barrier)
        if (c + 2 < NCHUNK)
            load_stage(sb, (c + 2) % GSTAGES, (c + 2) * 32,
                       Ahi, Alo, Bh, m0, n0, tid);

        uint32_t abase = sb + (uint32_t)(c % GSTAGES) * STAGE_B;
#pragma unroll
        for (int ks = 0; ks < 2; ks++) {
            uint32_t ah[2][4], al[2][4], bh[4][4];
#pragma unroll
            for (int mt = 0; mt < 2; mt++) {
                int row = warp_m * 32 + mt * 16 + (lane & 15);
                int ch = ks * 2 + (lane >> 4);
                uint32_t off = swz_off(row, ch);
                ldm4(ah[mt], abase + off);
                ldm4(al[mt], abase + TILE_B + off);
            }
#pragma unroll
            for (int p = 0; p < 4; p++) {
                int row = warp_n * 64 + (p * 2 + (lane >> 4)) * 8 + (lane & 7);
                int ch = ks * 2 + ((lane >> 3) & 1);
                ldm4(bh[p], abase + 2 * TILE_B + swz_off(row, ch));
            }
            // 2 passes over all 16 accumulators
#pragma unroll
            for (int mt = 0; mt < 2; mt++)
#pragma unroll
                for (int nt = 0; nt < 8; nt++)
                    mma16816h(acc[mt][nt], ah[mt], &bh[nt >> 1][(nt & 1) * 2]);
#pragma unroll
            for (int mt = 0; mt < 2; mt++)
#pragma unroll
                for (int nt = 0; nt < 8; nt++)
                    mma16816h(acc[mt][nt], al[mt], &bh[nt >> 1][(nt & 1) * 2]);
        }
    }

#pragma unroll
    for (int mt = 0; mt < 2; mt++) {
        int m = m0 + warp_m * 32 + mt * 16 + (lane >> 2);
#pragma unroll
        for (int nt = 0; nt < 8; nt++) {
            int n = n0 + warp_n * 64 + nt * 8 + (lane & 3) * 2;
            float b0 = bias[n], b1 = bias[n + 1];
            float f0 = acc[mt][nt][0] + b0, f1 = acc[mt][nt][1] + b1;
            float f2 = acc[mt][nt][2] + b0, f3 = acc[mt][nt][3] + b1;
            if (SPLIT_OUT) {
                __nv_bfloat16 h0 = __float2bfloat16(f0), h1 = __float2bfloat16(f1);
                __nv_bfloat16 h2 = __float2bfloat16(f2), h3 = __float2bfloat16(f3);
                *(uint32_t*)(Ch + (size_t)m * N + n) =
                    pack_bf16(__bfloat162float(h0), __bfloat162float(h1));
                *(uint32_t*)(Ch + (size_t)(m + 8) * N + n) =
                    pack_bf16(__bfloat162float(h2), __bfloat162float(h3));
                *(uint32_t*)(Cl + (size_t)m * N + n) =
                    pack_bf16(f0 - __bfloat162float(h0), f1 - __bfloat162float(h1));
                *(uint32_t*)(Cl + (size_t)(m + 8) * N + n) =
                    pack_bf16(f2 - __bfloat162float(h2), f3 - __bfloat162float(h3));
            } else {
                float2 o0 = {f0, f1}, o1 = {f2, f3};
                *(float2*)(C + (size_t)m * N + n) = o0;
                *(float2*)(C + (size_t)(m + 8) * N + n) = o1;
            }
        }
    }
}

// ---------------------------------------------------------------------------
// Tensor-core flash attention (causal), bf16 split x3 — unchanged core.
// Epilogue now emits fp16 hi/lo for the O-projection.
// ---------------------------------------------------------------------------
#define FA_TILE_B 8192                  // 64 rows * 128 B
#define FA_STAGE_B (4 * FA_TILE_B)      // Kh, Kl, Vh, Vl
#define FA_SMEM (2 * FA_STAGE_B)        // 65536

__device__ __forceinline__ uint32_t fswz(int row, int ch) {
    return (uint32_t)(row * 128 + ((ch ^ (row & 7)) << 4));
}

__device__ __forceinline__ void fa_load(
    uint32_t sb, int s, int k0,
    const __nv_bfloat16* __restrict__ qh, const __nv_bfloat16* __restrict__ ql,
    int b, int h, int tid)
{
    uint32_t base = sb + (uint32_t)s * FA_STAGE_B;
    const __nv_bfloat16* ptrs[4] = {qh, ql, qh, ql};
    int goff[4] = {1024, 1024, 2048, 2048};   // K hi/lo, V hi/lo
#pragma unroll
    for (int t = 0; t < 4; t++) {
        const __nv_bfloat16* p = ptrs[t];
        uint32_t tb = base + t * FA_TILE_B;
#pragma unroll
        for (int i = 0; i < 2; i++) {
            int idx = tid + i * 256;
            int row = idx >> 3;
            int ch = idx & 7;
            const void* g = p + (size_t)(b * TT + k0 + row) * TD3 + goff[t]
                          + h * 64 + ch * 8;
            cp16(tb + fswz(row, ch), g);
        }
    }
    cp_commit();
}

__global__ __launch_bounds__(256, 1) void flash_tc(
    const __nv_bfloat16* __restrict__ qkvh, const __nv_bfloat16* __restrict__ qkvl,
    __half* __restrict__ yh, __half* __restrict__ yl)
{
    extern __shared__ char smem[];
    uint32_t sb = smem_u32(smem);
    const int tid = threadIdx.x;
    const int wid = tid >> 5;
    const int lane = tid & 31;
    const int qt = (int)gridDim.x - 1 - (int)blockIdx.x;   // big tiles first
    const int bh = blockIdx.y;
    const int b = bh >> 4;
    const int h = bh & 15;
    const int q0 = qt * 128;

    const int ntile = 2 * (qt + 1);
    fa_load(sb, 0, 0, qkvh, qkvl, b, h, tid);   // 1 group in flight

    uint32_t qfh[4][4], qfl[4][4];
    {
        size_t r0g = (size_t)(b * TT + q0 + wid * 16 + (lane >> 2));
        const uint32_t* p0h = (const uint32_t*)(qkvh + r0g * TD3 + h * 64);
        const uint32_t* p1h = (const uint32_t*)(qkvh + (r0g + 8) * TD3 + h * 64);
        const uint32_t* p0l = (const uint32_t*)(qkvl + r0g * TD3 + h * 64);
        const uint32_t* p1l = (const uint32_t*)(qkvl + (r0g + 8) * TD3 + h * 64);
        int c2 = lane & 3;
#pragma unroll
        for (int ks = 0; ks < 4; ks++) {
            qfh[ks][0] = p0h[ks * 8 + c2];
            qfh[ks][1] = p1h[ks * 8 + c2];
            qfh[ks][2] = p0h[ks * 8 + c2 + 4];
            qfh[ks][3] = p1h[ks * 8 + c2 + 4];
            qfl[ks][0] = p0l[ks * 8 + c2];
            qfl[ks][1] = p1l[ks * 8 + c2];
            qfl[ks][2] = p0l[ks * 8 + c2 + 4];
            qfl[ks][3] = p1l[ks * 8 + c2 + 4];
        }
    }

    float acc_o[8][4];
#pragma unroll
    for (int i = 0; i < 8; i++)
#pragma unroll
        for (int j = 0; j < 4; j++) acc_o[i][j] = 0.f;
    float mr0 = -1e30f, mr1 = -1e30f, lr0 = 0.f, lr1 = 0.f;

    for (int kt = 0; kt < ntile; kt++) {
        const int s = kt & 1;
        const int k0 = kt * 64;
        cp_wait<0>();
        __syncthreads();
        if (kt + 1 < ntile)
            fa_load(sb, s ^ 1, (kt + 1) * 64, qkvh, qkvl, b, h, tid);

        uint32_t Kb = sb + (uint32_t)s * FA_STAGE_B;
        uint32_t Vb = Kb + 2 * FA_TILE_B;

        float accs[8][4];
#pragma unroll
        for (int i = 0; i < 8; i++)
#pragma unroll
            for (int j = 0; j < 4; j++) accs[i][j] = 0.f;

#pragma unroll
        for (int ks = 0; ks < 4; ks++) {
            uint32_t kfh[4][4], kfl[4][4];
#pragma unroll
            for (int j = 0; j < 4; j++) {
                int g = lane >> 3;
                int nt = 2 * j + (g >> 1);
                int kh = g & 1;
                int row = nt * 8 + (lane & 7);
                uint32_t off = fswz(row, ks * 2 + kh);
                ldm4(kfh[j], Kb + off);
                ldm4(kfl[j], Kb + FA_TILE_B + off);
            }
#pragma unroll
            for (int nt = 0; nt < 8; nt++)
                mma16816(accs[nt], qfh[ks], &kfh[nt >> 1][(nt & 1) * 2]);
#pragma unroll
            for (int nt = 0; nt < 8; nt++)
                mma16816(accs[nt], qfl[ks], &kfh[nt >> 1][(nt & 1) * 2]);
#pragma unroll
            for (int nt = 0; nt < 8; nt++)
                mma16816(accs[nt], qfh[ks], &kfl[nt >> 1][(nt & 1) * 2]);
        }

        const int qrow0 = q0 + wid * 16 + (lane >> 2);
        const bool diag = (k0 + 63 > q0 + wid * 16);
#pragma unroll
        for (int nt = 0; nt < 8; nt++) {
#pragma unroll
            for (int c = 0; c < 4; c++) {
                float v = accs[nt][c] * 0.125f;
                if (diag) {
                    int col = k0 + nt * 8 + 2 * (lane & 3) + (c & 1);
                    int row = qrow0 + ((c >> 1) << 3);
                    if (col > row) v = -1e30f;
                }
                accs[nt][c] = v;
            }
        }

        float mA = -1e30f, mB = -1e30f;
#pragma unroll
        for (int nt = 0; nt < 8; nt++) {
            mA = fmaxf(mA, fmaxf(accs[nt][0], accs[nt][1]));
            mB = fmaxf(mB, fmaxf(accs[nt][2], accs[nt][3]));
        }
        mA = fmaxf(mA, __shfl_xor_sync(0xffffffffu, mA, 1));
        mA = fmaxf(mA, __shfl_xor_sync(0xffffffffu, mA, 2));
        mB = fmaxf(mB, __shfl_xor_sync(0xffffffffu, mB, 1));
        mB = fmaxf(mB, __shfl_xor_sync(0xffffffffu, mB, 2));
        float mnA = fmaxf(mr0, mA), mnB = fmaxf(mr1, mB);
        float aA = __expf(mr0 - mnA), aB = __expf(mr1 - mnB);

        float psA = 0.f, psB = 0.f;
#pragma unroll
        for (int nt = 0; nt < 8; nt++) {
            accs[nt][0] = __expf(accs[nt][0] - mnA);
            accs[nt][1] = __expf(accs[nt][1] - mnA);
            accs[nt][2] = __expf(accs[nt][2] - mnB);
            accs[nt][3] = __expf(accs[nt][3] - mnB);
            psA += accs[nt][0] + accs[nt][1];
            psB += accs[nt][2] + accs[nt][3];
        }
        psA += __shfl_xor_sync(0xffffffffu, psA, 1);
        psA += __shfl_xor_sync(0xffffffffu, psA, 2);
        psB += __shfl_xor_sync(0xffffffffu, psB, 1);
        psB += __shfl_xor_sync(0xffffffffu, psB, 2);
        lr0 = lr0 * aA + psA;
        lr1 = lr1 * aB + psB;
        mr0 = mnA;
        mr1 = mnB;
#pragma unroll
        for (int nt = 0; nt < 8; nt++) {
            acc_o[nt][0] *= aA;
            acc_o[nt][1] *= aA;
            acc_o[nt][2] *= aB;
            acc_o[nt][3] *= aB;
        }

        uint32_t pfh[4][4], pfl[4][4];
#pragma unroll
        for (int ks = 0; ks < 4; ks++) {
#pragma unroll
            for (int half = 0; half < 2; half++) {
                int nt = 2 * ks + half;
                float f0 = accs[nt][0], f1 = accs[nt][1];
                float f2 = accs[nt][2], f3 = accs[nt][3];
                __nv_bfloat16 h0 = __float2bfloat16(f0), h1 = __float2bfloat16(f1);
                __nv_bfloat16 h2 = __float2bfloat16(f2), h3 = __float2bfloat16(f3);
                pfh[ks][half * 2 + 0] = pack_bf16(__bfloat162float(h0),
                                                 __bfloat162float(h1));
                pfh[ks][half * 2 + 1] = pack_bf16(__bfloat162float(h2),
                                                 __bfloat162float(h3));
                pfl[ks][half * 2 + 0] = pack_bf16(f0 - __bfloat162float(h0),
                                                  f1 - __bfloat162float(h1));
                pfl[ks][half * 2 + 1] = pack_bf16(f2 - __bfloat162float(h2),
                                                  f3 - __bfloat162float(h3));
            }
        }

#pragma unroll
        for (int ks = 0; ks < 4; ks++) {
            uint32_t vfh[4][4];
#pragma unroll
            for (int j = 0; j < 4; j++) {
                int g = lane >> 3;
                int nt = 2 * j + (g >> 1);
                int kh = g & 1;
                int row = ks * 16 + kh * 8 + (lane & 7);
                ldm4t(vfh[j], Vb + fswz(row, nt));
            }
#pragma unroll
            for (int nt = 0; nt < 8; nt++) {
                const uint32_t* bp = &vfh[nt >> 1][(nt & 1) * 2];
                mma16816(acc_o[nt], pfh[ks], bp);
                mma16816(acc_o[nt], pfl[ks], bp);
            }
            uint32_t vfl[4][4];
#pragma unroll
            for (int j = 0; j < 4; j++) {
                int g = lane >> 3;
                int nt = 2 * j + (g >> 1);
                int kh = g & 1;
                int row = ks * 16 + kh * 8 + (lane & 7);
                ldm4t(vfl[j], Vb + FA_TILE_B + fswz(row, nt));
            }
#pragma unroll
            for (int nt = 0; nt < 8; nt++)
                mma16816(acc_o[nt], pfh[ks], &vfl[nt >> 1][(nt & 1) * 2]);
        }
    }

    // ---- epilogue: normalize, split to fp16 hi/lo for O-projection ----
    float invA = 1.f / lr0, invB = 1.f / lr1;
    size_t rA = (size_t)(b * TT + q0 + wid * 16 + (lane >> 2));
    size_t rB = rA + 8;
#pragma unroll
    for (int nt = 0; nt < 8; nt++) {
        int col = h * 64 + nt * 8 + 2 * (lane & 3);
        float f0 = acc_o[nt][0] * invA, f1 = acc_o[nt][1] * invA;
        float f2 = acc_o[nt][2] * invB, f3 = acc_o[nt][3] * invB;
        __half h0 = __float2half_rn(f0), h1 = __float2half_rn(f1);
        __half h2 = __float2half_rn(f2), h3 = __float2half_rn(f3);
        *(uint32_t*)(yh + rA * DD + col) =
            pack_half(__half2float(h0), __half2float(h1));
        *(uint32_t*)(yh + rB * DD + col) =
            pack_half(__half2float(h2), __half2float(h3));
        *(uint32_t*)(yl + rA * DD + col) =
            pack_half(f0 - __half2float(h0), f1 - __half2float(h1));
        *(uint32_t*)(yl + rB * DD + col) =
            pack_half(f2 - __half2float(h2), f3 - __half2float(h3));
    }
}

// ---------------------------------------------------------------------------
// Launch
// ---------------------------------------------------------------------------
extern "C" void kernel_launch(void* const* d_in, const int* in_sizes, int n_in,
                              void* d_out, int out_size)
{
    const float* x     = (const float*)d_in[0];
    const float* W_qkv = (const float*)d_in[1];
    const float* b_qkv = (const float*)d_in[2];
    const float* W_o   = (const float*)d_in[3];
    const float* b_o   = (const float*)d_in[4];
    float* out = (float*)d_out;

    __nv_bfloat16 *qkvh, *qkvl;
    __half *xh, *xl, *yh, *yl, *wqh, *woh;
    cudaGetSymbolAddress((void**)&qkvh, g_qkvh);
    cudaGetSymbolAddress((void**)&qkvl, g_qkvl);
    cudaGetSymbolAddress((void**)&xh, g_xh);
    cudaGetSymbolAddress((void**)&xl, g_xl);
    cudaGetSymbolAddress((void**)&yh, g_yh);
    cudaGetSymbolAddress((void**)&yl, g_yl);
    cudaGetSymbolAddress((void**)&wqh, g_wqh);
    cudaGetSymbolAddress((void**)&woh, g_woh);

    cudaFuncSetAttribute(gemm_mma<true>, cudaFuncAttributeMaxDynamicSharedMemorySize,
                         GSMEM_BYTES);
    cudaFuncSetAttribute(gemm_mma<false>, cudaFuncAttributeMaxDynamicSharedMemorySize,
                         GSMEM_BYTES);
    cudaFuncSetAttribute(flash_tc, cudaFuncAttributeMaxDynamicSharedMemorySize,
                         FA_SMEM);

    // conversions
    split_f32h<<<(MM * KK / 4 + 255) / 256, 256>>>(x, xh, xl, MM * KK);
    transpose_h<<<dim3(TD3 / 32, KK / 32), dim3(32, 8)>>>(W_qkv, wqh, KK, TD3);
    transpose_h<<<dim3(DD / 32, KK / 32), dim3(32, 8)>>>(W_o, woh, KK, DD);

    // 1) QKV projection (fp16 2-term) -> split bf16 qkv
    gemm_mma<true><<<dim3(TD3 / 128, MM / 128), 256, GSMEM_BYTES>>>(
        xh, xl, wqh, b_qkv, nullptr, qkvh, qkvl, TD3);

    // 2) causal flash attention (bf16 x3) -> split fp16 y
    flash_tc<<<dim3(TT / 128, BB * HH), 256, FA_SMEM>>>(qkvh, qkvl, yh, yl);

    // 3) output projection (fp16 2-term) -> fp32 out
    gemm_mma<false><<<dim3(DD / 128, MM / 128), 256, GSMEM_BYTES>>>(
        yh, yl, woh, b_o, out, nullptr, nullptr, DD);
}

// round 8
// speedup vs baseline: 6.8789x; 1.2173x over previous
#include <cuda_runtime.h>
#include <cuda_bf16.h>
#include <cuda_fp16.h>
#include <cstdint>

// Problem constants (fixed by the reference)
#define BB 2
#define TT 2048
#define DD 1024
#define HH 16
#define DKK 64
#define TD3 3072    // 3*D
#define MM (BB*TT)  // 4096 rows
#define KK 1024     // GEMM K for both projections

// ---------------------------------------------------------------------------
// Scratch (allocation-free rule: __device__ globals)
// ---------------------------------------------------------------------------
__device__ __half g_qkvh[MM * TD3];          // qkv hi (fp16)
__device__ __half g_qkvl[MM * TD3];          // qkv lo (fp16; flash uses Q part)
__device__ __half g_xh[MM * KK];             // x split (fp16) for QKV GEMM
__device__ __half g_xl[MM * KK];
__device__ __half g_yh[MM * KK];             // attention out split (fp16)
__device__ __half g_yl[MM * KK];
__device__ __half g_wqh[TD3 * KK];           // W_qkv^T fp16, [N][K]
__device__ __half g_woh[DD * KK];            // W_o^T fp16, [N][K]

// ---------------------------------------------------------------------------
// PTX helpers (plain sm_100-legal: cp.async + ldmatrix + mma.sync)
// ---------------------------------------------------------------------------
__device__ __forceinline__ uint32_t smem_u32(const void* p) {
    uint32_t a;
    asm("{ .reg .u64 t; cvta.to.shared.u64 t, %1; cvt.u32.u64 %0, t; }"
        : "=r"(a) : "l"(p));
    return a;
}
__device__ __forceinline__ void cp16(uint32_t dst, const void* src) {
    asm volatile("cp.async.cg.shared.global [%0], [%1], 16;" :: "r"(dst), "l"(src));
}
__device__ __forceinline__ void cp_commit() {
    asm volatile("cp.async.commit_group;" ::: "memory");
}
template <int N>
__device__ __forceinline__ void cp_wait() {
    asm volatile("cp.async.wait_group %0;" :: "n"(N) : "memory");
}
__device__ __forceinline__ void ldm4(uint32_t* r, uint32_t addr) {
    asm volatile("ldmatrix.sync.aligned.m8n8.x4.shared.b16 {%0,%1,%2,%3}, [%4];"
                 : "=r"(r[0]), "=r"(r[1]), "=r"(r[2]), "=r"(r[3]) : "r"(addr));
}
__device__ __forceinline__ void ldm4t(uint32_t* r, uint32_t addr) {
    asm volatile("ldmatrix.sync.aligned.m8n8.x4.trans.shared.b16 {%0,%1,%2,%3}, [%4];"
                 : "=r"(r[0]), "=r"(r[1]), "=r"(r[2]), "=r"(r[3]) : "r"(addr));
}
// fp16 MMA
__device__ __forceinline__ void mma16816h(float* c, const uint32_t* a,
                                          const uint32_t* b) {
    asm volatile(
        "mma.sync.aligned.m16n8k16.row.col.f32.f16.f16.f32 "
        "{%0,%1,%2,%3}, {%4,%5,%6,%7}, {%8,%9}, {%0,%1,%2,%3};"
        : "+f"(c[0]), "+f"(c[1]), "+f"(c[2]), "+f"(c[3])
        : "r"(a[0]), "r"(a[1]), "r"(a[2]), "r"(a[3]), "r"(b[0]), "r"(b[1]));
}
__device__ __forceinline__ uint32_t pack_half(float a, float b) {
    __half2 t = __floats2half2_rn(a, b);             // .x = a (low)
    return *(uint32_t*)&t;
}

// ---------------------------------------------------------------------------
// Conversion kernels
// ---------------------------------------------------------------------------
struct __align__(8) h4 { __half v[4]; };

// fp32 -> (hi, lo) fp16 split
__global__ __launch_bounds__(256) void split_f32h(
    const float* __restrict__ src, __half* __restrict__ hi,
    __half* __restrict__ lo, int n)
{
    int i = (blockIdx.x * blockDim.x + threadIdx.x) * 4;
    if (i >= n) return;
    float4 v = *(const float4*)(src + i);
    h4 h, l;
    float vv[4] = {v.x, v.y, v.z, v.w};
#pragma unroll
    for (int j = 0; j < 4; j++) {
        __half a = __float2half_rn(vv[j]);
        h.v[j] = a;
        l.v[j] = __float2half_rn(vv[j] - __half2float(a));
    }
    *(h4*)(hi + i) = h;
    *(h4*)(lo + i) = l;
}

// W [K][N] fp32 -> Wt [N][K] fp16 (transpose, hi only)
__global__ __launch_bounds__(256) void transpose_h(
    const float* __restrict__ W, __half* __restrict__ T, int K, int N)
{
    __shared__ float t[32][33];
    int n0 = blockIdx.x * 32, k0 = blockIdx.y * 32;
    int tx = threadIdx.x, ty = threadIdx.y;
#pragma unroll
    for (int i = ty; i < 32; i += 8)
        t[i][tx] = W[(size_t)(k0 + i) * N + n0 + tx];
    __syncthreads();
#pragma unroll
    for (int i = ty; i < 32; i += 8)
        T[(size_t)(n0 + i) * K + k0 + tx] = __float2half_rn(t[tx][i]);
}

// ---------------------------------------------------------------------------
// fp16 2-term GEMM: C = (Ah+Al) @ Bh^T + bias.  A split fp16, B single fp16.
// 128x128 tile / CTA, BK=32, 3-stage cp.async, one sync per chunk.
// ---------------------------------------------------------------------------
#define TILE_B 8192                    // 128 rows * 64 B
#define STAGE_B (3 * TILE_B)           // Ahi, Alo, Bh
#define GSTAGES 3
#define GSMEM_BYTES (GSTAGES * STAGE_B)  // 73728
#define NCHUNK (KK / 32)               // 32

__device__ __forceinline__ uint32_t swz_off(int row, int chunk) {
    return (uint32_t)(row * 64 + ((chunk ^ ((row >> 1) & 3)) << 4));
}

__device__ __forceinline__ void load_stage(
    uint32_t sb, int s, int k0,
    const __half* __restrict__ Ahi, const __half* __restrict__ Alo,
    const __half* __restrict__ Bh, int m0, int n0, int tid)
{
    uint32_t base = sb + (uint32_t)s * STAGE_B;
    const __half* srcs[3] = {Ahi, Alo, Bh};
    int r0s[3] = {m0, m0, n0};
#pragma unroll
    for (int t = 0; t < 3; t++) {
        const __half* p = srcs[t];
        int r0 = r0s[t];
        uint32_t tb = base + t * TILE_B;
#pragma unroll
        for (int i = 0; i < 2; i++) {
            int c = tid + i * 256;
            int row = c >> 2;
            int ch = c & 3;
            const void* g = p + (size_t)(r0 + row) * KK + k0 + ch * 8;
            cp16(tb + swz_off(row, ch), g);
        }
    }
    cp_commit();
}

template <bool SPLIT_OUT>
__global__ __launch_bounds__(256, 2) void gemm_mma(
    const __half* __restrict__ Ahi, const __half* __restrict__ Alo,
    const __half* __restrict__ Bh,
    const float* __restrict__ bias, float* __restrict__ C,
    __half* __restrict__ Ch, __half* __restrict__ Cl, int N)
{
    extern __shared__ char smem[];
    uint32_t sb = smem_u32(smem);
    const int tid = threadIdx.x;
    const int wid = tid >> 5;
    const int lane = tid & 31;
    const int warp_m = wid >> 1;
    const int warp_n = wid & 1;
    const int n0 = blockIdx.x * 128;
    const int m0 = blockIdx.y * 128;

    float acc[2][8][4];
#pragma unroll
    for (int i = 0; i < 2; i++)
#pragma unroll
        for (int j = 0; j < 8; j++)
#pragma unroll
            for (int k = 0; k < 4; k++) acc[i][j][k] = 0.f;

    load_stage(sb, 0, 0, Ahi, Alo, Bh, m0, n0, tid);
    load_stage(sb, 1, 32, Ahi, Alo, Bh, m0, n0, tid);

    for (int c = 0; c < NCHUNK; c++) {
        if (c == NCHUNK - 1) cp_wait<0>(); else cp_wait<1>();
        __syncthreads();
        // load c+2 into buffer of c-1 (all warps finished it before barrier)
        if (c + 2 < NCHUNK)
            load_stage(sb, (c + 2) % GSTAGES, (c + 2) * 32,
                       Ahi, Alo, Bh, m0, n0, tid);

        uint32_t abase = sb + (uint32_t)(c % GSTAGES) * STAGE_B;
#pragma unroll
        for (int ks = 0; ks < 2; ks++) {
            uint32_t ah[2][4], al[2][4], bh[4][4];
#pragma unroll
            for (int mt = 0; mt < 2; mt++) {
                int row = warp_m * 32 + mt * 16 + (lane & 15);
                int ch = ks * 2 + (lane >> 4);
                uint32_t off = swz_off(row, ch);
                ldm4(ah[mt], abase + off);
                ldm4(al[mt], abase + TILE_B + off);
            }
#pragma unroll
            for (int p = 0; p < 4; p++) {
                int row = warp_n * 64 + (p * 2 + (lane >> 4)) * 8 + (lane & 7);
                int ch = ks * 2 + ((lane >> 3) & 1);
                ldm4(bh[p], abase + 2 * TILE_B + swz_off(row, ch));
            }
            // 2 passes over all 16 accumulators
#pragma unroll
            for (int mt = 0; mt < 2; mt++)
#pragma unroll
                for (int nt = 0; nt < 8; nt++)
                    mma16816h(acc[mt][nt], ah[mt], &bh[nt >> 1][(nt & 1) * 2]);
#pragma unroll
            for (int mt = 0; mt < 2; mt++)
#pragma unroll
                for (int nt = 0; nt < 8; nt++)
                    mma16816h(acc[mt][nt], al[mt], &bh[nt >> 1][(nt & 1) * 2]);
        }
    }

#pragma unroll
    for (int mt = 0; mt < 2; mt++) {
        int m = m0 + warp_m * 32 + mt * 16 + (lane >> 2);
#pragma unroll
        for (int nt = 0; nt < 8; nt++) {
            int n = n0 + warp_n * 64 + nt * 8 + (lane & 3) * 2;
            float b0 = bias[n], b1 = bias[n + 1];
            float f0 = acc[mt][nt][0] + b0, f1 = acc[mt][nt][1] + b1;
            float f2 = acc[mt][nt][2] + b0, f3 = acc[mt][nt][3] + b1;
            if (SPLIT_OUT) {
                __half h0 = __float2half_rn(f0), h1 = __float2half_rn(f1);
                __half h2 = __float2half_rn(f2), h3 = __float2half_rn(f3);
                *(uint32_t*)(Ch + (size_t)m * N + n) =
                    pack_half(__half2float(h0), __half2float(h1));
                *(uint32_t*)(Ch + (size_t)(m + 8) * N + n) =
                    pack_half(__half2float(h2), __half2float(h3));
                *(uint32_t*)(Cl + (size_t)m * N + n) =
                    pack_half(f0 - __half2float(h0), f1 - __half2float(h1));
                *(uint32_t*)(Cl + (size_t)(m + 8) * N + n) =
                    pack_half(f2 - __half2float(h2), f3 - __half2float(h3));
            } else {
                float2 o0 = {f0, f1}, o1 = {f2, f3};
                *(float2*)(C + (size_t)m * N + n) = o0;
                *(float2*)(C + (size_t)(m + 8) * N + n) = o1;
            }
        }
    }
}

// ---------------------------------------------------------------------------
// Tensor-core flash attention (causal), fp16.
// QK: Q split (hi/lo) x K single -> 2 MMA passes.
// PV: P single x V single -> 1 MMA pass.
// K/V single tiles double-buffered, one sync per tile.
// ---------------------------------------------------------------------------
#define FA_TILE_B 8192                  // 64 rows * 128 B
#define FA_STAGE_B (2 * FA_TILE_B)      // K, V
#define FA_SMEM (2 * FA_STAGE_B)        // 32768

__device__ __forceinline__ uint32_t fswz(int row, int ch) {
    return (uint32_t)(row * 128 + ((ch ^ (row & 7)) << 4));
}

__device__ __forceinline__ void fa_load(
    uint32_t sb, int s, int k0, const __half* __restrict__ qkvh,
    int b, int h, int tid)
{
    uint32_t base = sb + (uint32_t)s * FA_STAGE_B;
    int goff[2] = {1024, 2048};   // K, V
#pragma unroll
    for (int t = 0; t < 2; t++) {
        uint32_t tb = base + t * FA_TILE_B;
#pragma unroll
        for (int i = 0; i < 2; i++) {
            int idx = tid + i * 256;
            int row = idx >> 3;
            int ch = idx & 7;
            const void* g = qkvh + (size_t)(b * TT + k0 + row) * TD3 + goff[t]
                          + h * 64 + ch * 8;
            cp16(tb + fswz(row, ch), g);
        }
    }
    cp_commit();
}

__global__ __launch_bounds__(256, 1) void flash_tc(
    const __half* __restrict__ qkvh, const __half* __restrict__ qkvl,
    __half* __restrict__ yh, __half* __restrict__ yl)
{
    extern __shared__ char smem[];
    uint32_t sb = smem_u32(smem);
    const int tid = threadIdx.x;
    const int wid = tid >> 5;
    const int lane = tid & 31;
    const int qt = (int)gridDim.x - 1 - (int)blockIdx.x;   // big tiles first
    const int bh = blockIdx.y;
    const int b = bh >> 4;
    const int h = bh & 15;
    const int q0 = qt * 128;

    const int ntile = 2 * (qt + 1);
    fa_load(sb, 0, 0, qkvh, b, h, tid);   // 1 group in flight

    // ---- Q fragments (hi/lo fp16) straight from gmem ----
    uint32_t qfh[4][4], qfl[4][4];
    {
        size_t r0g = (size_t)(b * TT + q0 + wid * 16 + (lane >> 2));
        const uint32_t* p0h = (const uint32_t*)(qkvh + r0g * TD3 + h * 64);
        const uint32_t* p1h = (const uint32_t*)(qkvh + (r0g + 8) * TD3 + h * 64);
        const uint32_t* p0l = (const uint32_t*)(qkvl + r0g * TD3 + h * 64);
        const uint32_t* p1l = (const uint32_t*)(qkvl + (r0g + 8) * TD3 + h * 64);
        int c2 = lane & 3;
#pragma unroll
        for (int ks = 0; ks < 4; ks++) {
            qfh[ks][0] = p0h[ks * 8 + c2];
            qfh[ks][1] = p1h[ks * 8 + c2];
            qfh[ks][2] = p0h[ks * 8 + c2 + 4];
            qfh[ks][3] = p1h[ks * 8 + c2 + 4];
            qfl[ks][0] = p0l[ks * 8 + c2];
            qfl[ks][1] = p1l[ks * 8 + c2];
            qfl[ks][2] = p0l[ks * 8 + c2 + 4];
            qfl[ks][3] = p1l[ks * 8 + c2 + 4];
        }
    }

    float acc_o[8][4];
#pragma unroll
    for (int i = 0; i < 8; i++)
#pragma unroll
        for (int j = 0; j < 4; j++) acc_o[i][j] = 0.f;
    float mr0 = -1e30f, mr1 = -1e30f, lr0 = 0.f, lr1 = 0.f;

    for (int kt = 0; kt < ntile; kt++) {
        const int s = kt & 1;
        const int k0 = kt * 64;
        cp_wait<0>();
        __syncthreads();
        if (kt + 1 < ntile)
            fa_load(sb, s ^ 1, (kt + 1) * 64, qkvh, b, h, tid);

        uint32_t Kb = sb + (uint32_t)s * FA_STAGE_B;
        uint32_t Vb = Kb + FA_TILE_B;

        // ---- S = Q K^T (Q 2-term, K single) ----
        float accs[8][4];
#pragma unroll
        for (int i = 0; i < 8; i++)
#pragma unroll
            for (int j = 0; j < 4; j++) accs[i][j] = 0.f;

#pragma unroll
        for (int ks = 0; ks < 4; ks++) {
            uint32_t kf[4][4];
#pragma unroll
            for (int j = 0; j < 4; j++) {
                int g = lane >> 3;
                int nt = 2 * j + (g >> 1);
                int kh = g & 1;
                int row = nt * 8 + (lane & 7);
                ldm4(kf[j], Kb + fswz(row, ks * 2 + kh));
            }
#pragma unroll
            for (int nt = 0; nt < 8; nt++)
                mma16816h(accs[nt], qfh[ks], &kf[nt >> 1][(nt & 1) * 2]);
#pragma unroll
            for (int nt = 0; nt < 8; nt++)
                mma16816h(accs[nt], qfl[ks], &kf[nt >> 1][(nt & 1) * 2]);
        }

        // ---- scale + causal mask ----
        const int qrow0 = q0 + wid * 16 + (lane >> 2);
        const bool diag = (k0 + 63 > q0 + wid * 16);
#pragma unroll
        for (int nt = 0; nt < 8; nt++) {
#pragma unroll
            for (int c = 0; c < 4; c++) {
                float v = accs[nt][c] * 0.125f;
                if (diag) {
                    int col = k0 + nt * 8 + 2 * (lane & 3) + (c & 1);
                    int row = qrow0 + ((c >> 1) << 3);
                    if (col > row) v = -1e30f;
                }
                accs[nt][c] = v;
            }
        }

        // ---- online softmax ----
        float mA = -1e30f, mB = -1e30f;
#pragma unroll
        for (int nt = 0; nt < 8; nt++) {
            mA = fmaxf(mA, fmaxf(accs[nt][0], accs[nt][1]));
            mB = fmaxf(mB, fmaxf(accs[nt][2], accs[nt][3]));
        }
        mA = fmaxf(mA, __shfl_xor_sync(0xffffffffu, mA, 1));
        mA = fmaxf(mA, __shfl_xor_sync(0xffffffffu, mA, 2));
        mB = fmaxf(mB, __shfl_xor_sync(0xffffffffu, mB, 1));
        mB = fmaxf(mB, __shfl_xor_sync(0xffffffffu, mB, 2));
        float mnA = fmaxf(mr0, mA), mnB = fmaxf(mr1, mB);
        float aA = __expf(mr0 - mnA), aB = __expf(mr1 - mnB);

        float psA = 0.f, psB = 0.f;
#pragma unroll
        for (int nt = 0; nt < 8; nt++) {
            accs[nt][0] = __expf(accs[nt][0] - mnA);
            accs[nt][1] = __expf(accs[nt][1] - mnA);
            accs[nt][2] = __expf(accs[nt][2] - mnB);
            accs[nt][3] = __expf(accs[nt][3] - mnB);
            psA += accs[nt][0] + accs[nt][1];
            psB += accs[nt][2] + accs[nt][3];
        }
        psA += __shfl_xor_sync(0xffffffffu, psA, 1);
        psA += __shfl_xor_sync(0xffffffffu, psA, 2);
        psB += __shfl_xor_sync(0xffffffffu, psB, 1);
        psB += __shfl_xor_sync(0xffffffffu, psB, 2);
        lr0 = lr0 * aA + psA;
        lr1 = lr1 * aB + psB;
        mr0 = mnA;
        mr1 = mnB;
#pragma unroll
        for (int nt = 0; nt < 8; nt++) {
            acc_o[nt][0] *= aA;
            acc_o[nt][1] *= aA;
            acc_o[nt][2] *= aB;
            acc_o[nt][3] *= aB;
        }

        // ---- P -> fp16 single a-fragments ----
        uint32_t pf[4][4];
#pragma unroll
        for (int ks = 0; ks < 4; ks++) {
#pragma unroll
            for (int half = 0; half < 2; half++) {
                int nt = 2 * ks + half;
                pf[ks][half * 2 + 0] = pack_half(accs[nt][0], accs[nt][1]);
                pf[ks][half * 2 + 1] = pack_half(accs[nt][2], accs[nt][3]);
            }
        }

        // ---- O += P V (single x single), V frags via ldmatrix.trans ----
#pragma unroll
        for (int ks = 0; ks < 4; ks++) {
            uint32_t vf[4][4];
#pragma unroll
            for (int j = 0; j < 4; j++) {
                int g = lane >> 3;
                int nt = 2 * j + (g >> 1);
                int kh = g & 1;
                int row = ks * 16 + kh * 8 + (lane & 7);
                ldm4t(vf[j], Vb + fswz(row, nt));
            }
#pragma unroll
            for (int nt = 0; nt < 8; nt++)
                mma16816h(acc_o[nt], pf[ks], &vf[nt >> 1][(nt & 1) * 2]);
        }
    }

    // ---- epilogue: normalize, split to fp16 hi/lo for O-projection ----
    float invA = 1.f / lr0, invB = 1.f / lr1;
    size_t rA = (size_t)(b * TT + q0 + wid * 16 + (lane >> 2));
    size_t rB = rA + 8;
#pragma unroll
    for (int nt = 0; nt < 8; nt++) {
        int col = h * 64 + nt * 8 + 2 * (lane & 3);
        float f0 = acc_o[nt][0] * invA, f1 = acc_o[nt][1] * invA;
        float f2 = acc_o[nt][2] * invB, f3 = acc_o[nt][3] * invB;
        __half h0 = __float2half_rn(f0), h1 = __float2half_rn(f1);
        __half h2 = __float2half_rn(f2), h3 = __float2half_rn(f3);
        *(uint32_t*)(yh + rA * DD + col) =
            pack_half(__half2float(h0), __half2float(h1));
        *(uint32_t*)(yh + rB * DD + col) =
            pack_half(__half2float(h2), __half2float(h3));
        *(uint32_t*)(yl + rA * DD + col) =
            pack_half(f0 - __half2float(h0), f1 - __half2float(h1));
        *(uint32_t*)(yl + rB * DD + col) =
            pack_half(f2 - __half2float(h2), f3 - __half2float(h3));
    }
}

// ---------------------------------------------------------------------------
// Launch
// ---------------------------------------------------------------------------
extern "C" void kernel_launch(void* const* d_in, const int* in_sizes, int n_in,
                              void* d_out, int out_size)
{
    const float* x     = (const float*)d_in[0];
    const float* W_qkv = (const float*)d_in[1];
    const float* b_qkv = (const float*)d_in[2];
    const float* W_o   = (const float*)d_in[3];
    const float* b_o   = (const float*)d_in[4];
    float* out = (float*)d_out;

    __half *qkvh, *qkvl, *xh, *xl, *yh, *yl, *wqh, *woh;
    cudaGetSymbolAddress((void**)&qkvh, g_qkvh);
    cudaGetSymbolAddress((void**)&qkvl, g_qkvl);
    cudaGetSymbolAddress((void**)&xh, g_xh);
    cudaGetSymbolAddress((void**)&xl, g_xl);
    cudaGetSymbolAddress((void**)&yh, g_yh);
    cudaGetSymbolAddress((void**)&yl, g_yl);
    cudaGetSymbolAddress((void**)&wqh, g_wqh);
    cudaGetSymbolAddress((void**)&woh, g_woh);

    cudaFuncSetAttribute(gemm_mma<true>, cudaFuncAttributeMaxDynamicSharedMemorySize,
                         GSMEM_BYTES);
    cudaFuncSetAttribute(gemm_mma<false>, cudaFuncAttributeMaxDynamicSharedMemorySize,
                         GSMEM_BYTES);
    cudaFuncSetAttribute(flash_tc, cudaFuncAttributeMaxDynamicSharedMemorySize,
                         FA_SMEM);

    // conversions
    split_f32h<<<(MM * KK / 4 + 255) / 256, 256>>>(x, xh, xl, MM * KK);
    transpose_h<<<dim3(TD3 / 32, KK / 32), dim3(32, 8)>>>(W_qkv, wqh, KK, TD3);
    transpose_h<<<dim3(DD / 32, KK / 32), dim3(32, 8)>>>(W_o, woh, KK, DD);

    // 1) QKV projection (fp16 2-term) -> split fp16 qkv
    gemm_mma<true><<<dim3(TD3 / 128, MM / 128), 256, GSMEM_BYTES>>>(
        xh, xl, wqh, b_qkv, nullptr, qkvh, qkvl, TD3);

    // 2) causal flash attention (fp16: QK 2-pass, PV 1-pass) -> split fp16 y
    flash_tc<<<dim3(TT / 128, BB * HH), 256, FA_SMEM>>>(qkvh, qkvl, yh, yl);

    // 3) output projection (fp16 2-term) -> fp32 out
    gemm_mma<false><<<dim3(DD / 128, MM / 128), 256, GSMEM_BYTES>>>(
        yh, yl, woh, b_o, out, nullptr, nullptr, DD);
}

// round 9
// speedup vs baseline: 9.9480x; 1.4462x over previous
#include <cuda_runtime.h>
#include <cuda_bf16.h>
#include <cuda_fp16.h>
#include <cstdint>

// Problem constants (fixed by the reference)
#define BB 2
#define TT 2048
#define DD 1024
#define HH 16
#define DKK 64
#define TD3 3072    // 3*D
#define MM (BB*TT)  // 4096 rows
#define KK 1024     // GEMM K for both projections

// ---------------------------------------------------------------------------
// Scratch (allocation-free rule: __device__ globals)
// ---------------------------------------------------------------------------
__device__ __half g_qkv[MM * TD3];           // qkv fp16
__device__ __half g_x[MM * KK];              // x fp16
__device__ __half g_y[MM * KK];              // attention out fp16
__device__ __half g_wqh[TD3 * KK];           // W_qkv^T fp16, [N][K]
__device__ __half g_woh[DD * KK];            // W_o^T fp16, [N][K]

// ---------------------------------------------------------------------------
// PTX helpers (plain sm_100-legal: cp.async + ldmatrix + mma.sync)
// ---------------------------------------------------------------------------
__device__ __forceinline__ uint32_t smem_u32(const void* p) {
    uint32_t a;
    asm("{ .reg .u64 t; cvta.to.shared.u64 t, %1; cvt.u32.u64 %0, t; }"
        : "=r"(a) : "l"(p));
    return a;
}
__device__ __forceinline__ void cp16(uint32_t dst, const void* src) {
    asm volatile("cp.async.cg.shared.global [%0], [%1], 16;" :: "r"(dst), "l"(src));
}
__device__ __forceinline__ void cp_commit() {
    asm volatile("cp.async.commit_group;" ::: "memory");
}
template <int N>
__device__ __forceinline__ void cp_wait() {
    asm volatile("cp.async.wait_group %0;" :: "n"(N) : "memory");
}
__device__ __forceinline__ void ldm4(uint32_t* r, uint32_t addr) {
    asm volatile("ldmatrix.sync.aligned.m8n8.x4.shared.b16 {%0,%1,%2,%3}, [%4];"
                 : "=r"(r[0]), "=r"(r[1]), "=r"(r[2]), "=r"(r[3]) : "r"(addr));
}
__device__ __forceinline__ void ldm4t(uint32_t* r, uint32_t addr) {
    asm volatile("ldmatrix.sync.aligned.m8n8.x4.trans.shared.b16 {%0,%1,%2,%3}, [%4];"
                 : "=r"(r[0]), "=r"(r[1]), "=r"(r[2]), "=r"(r[3]) : "r"(addr));
}
// fp16 MMA
__device__ __forceinline__ void mma16816h(float* c, const uint32_t* a,
                                          const uint32_t* b) {
    asm volatile(
        "mma.sync.aligned.m16n8k16.row.col.f32.f16.f16.f32 "
        "{%0,%1,%2,%3}, {%4,%5,%6,%7}, {%8,%9}, {%0,%1,%2,%3};"
        : "+f"(c[0]), "+f"(c[1]), "+f"(c[2]), "+f"(c[3])
        : "r"(a[0]), "r"(a[1]), "r"(a[2]), "r"(a[3]), "r"(b[0]), "r"(b[1]));
}
__device__ __forceinline__ uint32_t pack_half(float a, float b) {
    __half2 t = __floats2half2_rn(a, b);             // .x = a (low)
    return *(uint32_t*)&t;
}

// ---------------------------------------------------------------------------
// Conversion kernels
// ---------------------------------------------------------------------------
struct __align__(8) h4 { __half v[4]; };

// fp32 -> fp16
__global__ __launch_bounds__(256) void convert_f32h(
    const float* __restrict__ src, __half* __restrict__ dst, int n)
{
    int i = (blockIdx.x * blockDim.x + threadIdx.x) * 4;
    if (i >= n) return;
    float4 v = *(const float4*)(src + i);
    h4 h;
    h.v[0] = __float2half_rn(v.x);
    h.v[1] = __float2half_rn(v.y);
    h.v[2] = __float2half_rn(v.z);
    h.v[3] = __float2half_rn(v.w);
    *(h4*)(dst + i) = h;
}

// W [K][N] fp32 -> Wt [N][K] fp16 (transpose)
__global__ __launch_bounds__(256) void transpose_h(
    const float* __restrict__ W, __half* __restrict__ T, int K, int N)
{
    __shared__ float t[32][33];
    int n0 = blockIdx.x * 32, k0 = blockIdx.y * 32;
    int tx = threadIdx.x, ty = threadIdx.y;
#pragma unroll
    for (int i = ty; i < 32; i += 8)
        t[i][tx] = W[(size_t)(k0 + i) * N + n0 + tx];
    __syncthreads();
#pragma unroll
    for (int i = ty; i < 32; i += 8)
        T[(size_t)(n0 + i) * K + k0 + tx] = __float2half_rn(t[tx][i]);
}

// ---------------------------------------------------------------------------
// fp16 single-pass GEMM: C = A @ B^T + bias.
// 128x128 tile / CTA, BK=32, 3-stage cp.async, one sync per chunk.
// ---------------------------------------------------------------------------
#define TILE_B 8192                    // 128 rows * 64 B
#define STAGE_B (2 * TILE_B)           // A, B
#define GSTAGES 3
#define GSMEM_BYTES (GSTAGES * STAGE_B)  // 49152
#define NCHUNK (KK / 32)               // 32

__device__ __forceinline__ uint32_t swz_off(int row, int chunk) {
    return (uint32_t)(row * 64 + ((chunk ^ ((row >> 1) & 3)) << 4));
}

__device__ __forceinline__ void load_stage(
    uint32_t sb, int s, int k0,
    const __half* __restrict__ A, const __half* __restrict__ Bh,
    int m0, int n0, int tid)
{
    uint32_t base = sb + (uint32_t)s * STAGE_B;
    const __half* srcs[2] = {A, Bh};
    int r0s[2] = {m0, n0};
#pragma unroll
    for (int t = 0; t < 2; t++) {
        const __half* p = srcs[t];
        int r0 = r0s[t];
        uint32_t tb = base + t * TILE_B;
#pragma unroll
        for (int i = 0; i < 2; i++) {
            int c = tid + i * 256;
            int row = c >> 2;
            int ch = c & 3;
            const void* g = p + (size_t)(r0 + row) * KK + k0 + ch * 8;
            cp16(tb + swz_off(row, ch), g);
        }
    }
    cp_commit();
}

template <bool HALF_OUT>
__global__ __launch_bounds__(256, 2) void gemm_mma(
    const __half* __restrict__ A, const __half* __restrict__ Bh,
    const float* __restrict__ bias, float* __restrict__ C,
    __half* __restrict__ Ch, int N)
{
    extern __shared__ char smem[];
    uint32_t sb = smem_u32(smem);
    const int tid = threadIdx.x;
    const int wid = tid >> 5;
    const int lane = tid & 31;
    const int warp_m = wid >> 1;
    const int warp_n = wid & 1;
    const int n0 = blockIdx.x * 128;
    const int m0 = blockIdx.y * 128;

    float acc[2][8][4];
#pragma unroll
    for (int i = 0; i < 2; i++)
#pragma unroll
        for (int j = 0; j < 8; j++)
#pragma unroll
            for (int k = 0; k < 4; k++) acc[i][j][k] = 0.f;

    load_stage(sb, 0, 0, A, Bh, m0, n0, tid);
    load_stage(sb, 1, 32, A, Bh, m0, n0, tid);

    for (int c = 0; c < NCHUNK; c++) {
        if (c == NCHUNK - 1) cp_wait<0>(); else cp_wait<1>();
        __syncthreads();
        // load c+2 into buffer of c-1 (all warps finished it before barrier)
        if (c + 2 < NCHUNK)
            load_stage(sb, (c + 2) % GSTAGES, (c + 2) * 32, A, Bh, m0, n0, tid);

        uint32_t abase = sb + (uint32_t)(c % GSTAGES) * STAGE_B;
#pragma unroll
        for (int ks = 0; ks < 2; ks++) {
            uint32_t ah[2][4], bh[4][4];
#pragma unroll
            for (int mt = 0; mt < 2; mt++) {
                int row = warp_m * 32 + mt * 16 + (lane & 15);
                int ch = ks * 2 + (lane >> 4);
                ldm4(ah[mt], abase + swz_off(row, ch));
            }
#pragma unroll
            for (int p = 0; p < 4; p++) {
                int row = warp_n * 64 + (p * 2 + (lane >> 4)) * 8 + (lane & 7);
                int ch = ks * 2 + ((lane >> 3) & 1);
                ldm4(bh[p], abase + TILE_B + swz_off(row, ch));
            }
#pragma unroll
            for (int mt = 0; mt < 2; mt++)
#pragma unroll
                for (int nt = 0; nt < 8; nt++)
                    mma16816h(acc[mt][nt], ah[mt], &bh[nt >> 1][(nt & 1) * 2]);
        }
    }

#pragma unroll
    for (int mt = 0; mt < 2; mt++) {
        int m = m0 + warp_m * 32 + mt * 16 + (lane >> 2);
#pragma unroll
        for (int nt = 0; nt < 8; nt++) {
            int n = n0 + warp_n * 64 + nt * 8 + (lane & 3) * 2;
            float b0 = bias[n], b1 = bias[n + 1];
            float f0 = acc[mt][nt][0] + b0, f1 = acc[mt][nt][1] + b1;
            float f2 = acc[mt][nt][2] + b0, f3 = acc[mt][nt][3] + b1;
            if (HALF_OUT) {
                *(uint32_t*)(Ch + (size_t)m * N + n) = pack_half(f0, f1);
                *(uint32_t*)(Ch + (size_t)(m + 8) * N + n) = pack_half(f2, f3);
            } else {
                float2 o0 = {f0, f1}, o1 = {f2, f3};
                *(float2*)(C + (size_t)m * N + n) = o0;
                *(float2*)(C + (size_t)(m + 8) * N + n) = o1;
            }
        }
    }
}

// ---------------------------------------------------------------------------
// Tensor-core flash attention (causal), fp16 single-pass:
// QK: Q single x K single -> 1 MMA pass.  PV: P single x V single -> 1 pass.
// K/V tiles double-buffered, one sync per tile.
// ---------------------------------------------------------------------------
#define FA_TILE_B 8192                  // 64 rows * 128 B
#define FA_STAGE_B (2 * FA_TILE_B)      // K, V
#define FA_SMEM (2 * FA_STAGE_B)        // 32768

__device__ __forceinline__ uint32_t fswz(int row, int ch) {
    return (uint32_t)(row * 128 + ((ch ^ (row & 7)) << 4));
}

__device__ __forceinline__ void fa_load(
    uint32_t sb, int s, int k0, const __half* __restrict__ qkv,
    int b, int h, int tid)
{
    uint32_t base = sb + (uint32_t)s * FA_STAGE_B;
    int goff[2] = {1024, 2048};   // K, V
#pragma unroll
    for (int t = 0; t < 2; t++) {
        uint32_t tb = base + t * FA_TILE_B;
#pragma unroll
        for (int i = 0; i < 2; i++) {
            int idx = tid + i * 256;
            int row = idx >> 3;
            int ch = idx & 7;
            const void* g = qkv + (size_t)(b * TT + k0 + row) * TD3 + goff[t]
                          + h * 64 + ch * 8;
            cp16(tb + fswz(row, ch), g);
        }
    }
    cp_commit();
}

__global__ __launch_bounds__(256, 1) void flash_tc(
    const __half* __restrict__ qkv, __half* __restrict__ y)
{
    extern __shared__ char smem[];
    uint32_t sb = smem_u32(smem);
    const int tid = threadIdx.x;
    const int wid = tid >> 5;
    const int lane = tid & 31;
    const int qt = (int)gridDim.x - 1 - (int)blockIdx.x;   // big tiles first
    const int bh = blockIdx.y;
    const int b = bh >> 4;
    const int h = bh & 15;
    const int q0 = qt * 128;

    const int ntile = 2 * (qt + 1);
    fa_load(sb, 0, 0, qkv, b, h, tid);   // 1 group in flight

    // ---- Q fragments (fp16) straight from gmem ----
    uint32_t qf[4][4];
    {
        size_t r0g = (size_t)(b * TT + q0 + wid * 16 + (lane >> 2));
        const uint32_t* p0 = (const uint32_t*)(qkv + r0g * TD3 + h * 64);
        const uint32_t* p1 = (const uint32_t*)(qkv + (r0g + 8) * TD3 + h * 64);
        int c2 = lane & 3;
#pragma unroll
        for (int ks = 0; ks < 4; ks++) {
            qf[ks][0] = p0[ks * 8 + c2];
            qf[ks][1] = p1[ks * 8 + c2];
            qf[ks][2] = p0[ks * 8 + c2 + 4];
            qf[ks][3] = p1[ks * 8 + c2 + 4];
        }
    }

    float acc_o[8][4];
#pragma unroll
    for (int i = 0; i < 8; i++)
#pragma unroll
        for (int j = 0; j < 4; j++) acc_o[i][j] = 0.f;
    float mr0 = -1e30f, mr1 = -1e30f, lr0 = 0.f, lr1 = 0.f;

    for (int kt = 0; kt < ntile; kt++) {
        const int s = kt & 1;
        const int k0 = kt * 64;
        cp_wait<0>();
        __syncthreads();
        if (kt + 1 < ntile)
            fa_load(sb, s ^ 1, (kt + 1) * 64, qkv, b, h, tid);

        uint32_t Kb = sb + (uint32_t)s * FA_STAGE_B;
        uint32_t Vb = Kb + FA_TILE_B;

        // ---- S = Q K^T (single pass) ----
        float accs[8][4];
#pragma unroll
        for (int i = 0; i < 8; i++)
#pragma unroll
            for (int j = 0; j < 4; j++) accs[i][j] = 0.f;

#pragma unroll
        for (int ks = 0; ks < 4; ks++) {
            uint32_t kf[4][4];
#pragma unroll
            for (int j = 0; j < 4; j++) {
                int g = lane >> 3;
                int nt = 2 * j + (g >> 1);
                int kh = g & 1;
                int row = nt * 8 + (lane & 7);
                ldm4(kf[j], Kb + fswz(row, ks * 2 + kh));
            }
#pragma unroll
            for (int nt = 0; nt < 8; nt++)
                mma16816h(accs[nt], qf[ks], &kf[nt >> 1][(nt & 1) * 2]);
        }

        // ---- scale + causal mask ----
        const int qrow0 = q0 + wid * 16 + (lane >> 2);
        const bool diag = (k0 + 63 > q0 + wid * 16);
#pragma unroll
        for (int nt = 0; nt < 8; nt++) {
#pragma unroll
            for (int c = 0; c < 4; c++) {
                float v = accs[nt][c] * 0.125f;
                if (diag) {
                    int col = k0 + nt * 8 + 2 * (lane & 3) + (c & 1);
                    int row = qrow0 + ((c >> 1) << 3);
                    if (col > row) v = -1e30f;
                }
                accs[nt][c] = v;
            }
        }

        // ---- online softmax ----
        float mA = -1e30f, mB = -1e30f;
#pragma unroll
        for (int nt = 0; nt < 8; nt++) {
            mA = fmaxf(mA, fmaxf(accs[nt][0], accs[nt][1]));
            mB = fmaxf(mB, fmaxf(accs[nt][2], accs[nt][3]));
        }
        mA = fmaxf(mA, __shfl_xor_sync(0xffffffffu, mA, 1));
        mA = fmaxf(mA, __shfl_xor_sync(0xffffffffu, mA, 2));
        mB = fmaxf(mB, __shfl_xor_sync(0xffffffffu, mB, 1));
        mB = fmaxf(mB, __shfl_xor_sync(0xffffffffu, mB, 2));
        float mnA = fmaxf(mr0, mA), mnB = fmaxf(mr1, mB);
        float aA = __expf(mr0 - mnA), aB = __expf(mr1 - mnB);

        float psA = 0.f, psB = 0.f;
#pragma unroll
        for (int nt = 0; nt < 8; nt++) {
            accs[nt][0] = __expf(accs[nt][0] - mnA);
            accs[nt][1] = __expf(accs[nt][1] - mnA);
            accs[nt][2] = __expf(accs[nt][2] - mnB);
            accs[nt][3] = __expf(accs[nt][3] - mnB);
            psA += accs[nt][0] + accs[nt][1];
            psB += accs[nt][2] + accs[nt][3];
        }
        psA += __shfl_xor_sync(0xffffffffu, psA, 1);
        psA += __shfl_xor_sync(0xffffffffu, psA, 2);
        psB += __shfl_xor_sync(0xffffffffu, psB, 1);
        psB += __shfl_xor_sync(0xffffffffu, psB, 2);
        lr0 = lr0 * aA + psA;
        lr1 = lr1 * aB + psB;
        mr0 = mnA;
        mr1 = mnB;
#pragma unroll
        for (int nt = 0; nt < 8; nt++) {
            acc_o[nt][0] *= aA;
            acc_o[nt][1] *= aA;
            acc_o[nt][2] *= aB;
            acc_o[nt][3] *= aB;
        }

        // ---- P -> fp16 a-fragments ----
        uint32_t pf[4][4];
#pragma unroll
        for (int ks = 0; ks < 4; ks++) {
#pragma unroll
            for (int half = 0; half < 2; half++) {
                int nt = 2 * ks + half;
                pf[ks][half * 2 + 0] = pack_half(accs[nt][0], accs[nt][1]);
                pf[ks][half * 2 + 1] = pack_half(accs[nt][2], accs[nt][3]);
            }
        }

        // ---- O += P V (single pass), V frags via ldmatrix.trans ----
#pragma unroll
        for (int ks = 0; ks < 4; ks++) {
            uint32_t vf[4][4];
#pragma unroll
            for (int j = 0; j < 4; j++) {
                int g = lane >> 3;
                int nt = 2 * j + (g >> 1);
                int kh = g & 1;
                int row = ks * 16 + kh * 8 + (lane & 7);
                ldm4t(vf[j], Vb + fswz(row, nt));
            }
#pragma unroll
            for (int nt = 0; nt < 8; nt++)
                mma16816h(acc_o[nt], pf[ks], &vf[nt >> 1][(nt & 1) * 2]);
        }
    }

    // ---- epilogue: normalize, store fp16 y ----
    float invA = 1.f / lr0, invB = 1.f / lr1;
    size_t rA = (size_t)(b * TT + q0 + wid * 16 + (lane >> 2));
    size_t rB = rA + 8;
#pragma unroll
    for (int nt = 0; nt < 8; nt++) {
        int col = h * 64 + nt * 8 + 2 * (lane & 3);
        *(uint32_t*)(y + rA * DD + col) =
            pack_half(acc_o[nt][0] * invA, acc_o[nt][1] * invA);
        *(uint32_t*)(y + rB * DD + col) =
            pack_half(acc_o[nt][2] * invB, acc_o[nt][3] * invB);
    }
}

// ---------------------------------------------------------------------------
// Launch
// ---------------------------------------------------------------------------
extern "C" void kernel_launch(void* const* d_in, const int* in_sizes, int n_in,
                              void* d_out, int out_size)
{
    const float* x     = (const float*)d_in[0];
    const float* W_qkv = (const float*)d_in[1];
    const float* b_qkv = (const float*)d_in[2];
    const float* W_o   = (const float*)d_in[3];
    const float* b_o   = (const float*)d_in[4];
    float* out = (float*)d_out;

    __half *qkv, *xh, *yh, *wqh, *woh;
    cudaGetSymbolAddress((void**)&qkv, g_qkv);
    cudaGetSymbolAddress((void**)&xh, g_x);
    cudaGetSymbolAddress((void**)&yh, g_y);
    cudaGetSymbolAddress((void**)&wqh, g_wqh);
    cudaGetSymbolAddress((void**)&woh, g_woh);

    cudaFuncSetAttribute(gemm_mma<true>, cudaFuncAttributeMaxDynamicSharedMemorySize,
                         GSMEM_BYTES);
    cudaFuncSetAttribute(gemm_mma<false>, cudaFuncAttributeMaxDynamicSharedMemorySize,
                         GSMEM_BYTES);
    cudaFuncSetAttribute(flash_tc, cudaFuncAttributeMaxDynamicSharedMemorySize,
                         FA_SMEM);

    // conversions
    convert_f32h<<<(MM * KK / 4 + 255) / 256, 256>>>(x, xh, MM * KK);
    transpose_h<<<dim3(TD3 / 32, KK / 32), dim3(32, 8)>>>(W_qkv, wqh, KK, TD3);
    transpose_h<<<dim3(DD / 32, KK / 32), dim3(32, 8)>>>(W_o, woh, KK, DD);

    // 1) QKV projection (fp16 single pass) -> fp16 qkv
    gemm_mma<true><<<dim3(TD3 / 128, MM / 128), 256, GSMEM_BYTES>>>(
        xh, wqh, b_qkv, nullptr, qkv, TD3);

    // 2) causal flash attention (fp16 single pass) -> fp16 y
    flash_tc<<<dim3(TT / 128, BB * HH), 256, FA_SMEM>>>(qkv, yh);

    // 3) output projection (fp16 single pass) -> fp32 out
    gemm_mma<false><<<dim3(DD / 128, MM / 128), 256, GSMEM_BYTES>>>(
        yh, woh, b_o, out, nullptr, DD);
}